// round 10
// baseline (speedup 1.0000x reference)
#include <cuda_runtime.h>
#include <cuda_fp16.h>
#include <math.h>
#include <stdint.h>

// Problem constants
#define B_   16
#define S_   4096
#define D_   1024
#define M_   (B_ * S_)
#define NBC_ 8               // n partial blocks (1024 / 128)

// ---------------- device scratch ----------------
__device__ float g_dec_feat[B_ * D_];
__device__ float g_score_part[NBC_ * M_];
__device__ float g_ctx_part[32 * B_ * D_];
__device__ __align__(16) __half g_enc_h[(size_t)M_ * D_];   // fp16 mirror of encoder
__device__ __align__(16) __half g_wh_h[(size_t)D_ * D_];    // fp16 mirror of W_h

// ================= PTX helpers (plain sm_100-safe) =================
__device__ __forceinline__ uint32_t smem_u32(const void* p) {
    uint32_t a;
    asm("{ .reg .u64 t; cvta.to.shared.u64 t, %1; cvt.u32.u64 %0, t; }" : "=r"(a) : "l"(p));
    return a;
}

#define CP_ASYNC16(dst, src) \
    asm volatile("cp.async.cg.shared.global [%0], [%1], 16;" :: "r"(dst), "l"(src) : "memory")
#define CP_COMMIT() asm volatile("cp.async.commit_group;" ::: "memory")
#define CP_WAIT2()  asm volatile("cp.async.wait_group 2;" ::: "memory")

#define LDSM4(r, addr) \
    asm volatile("ldmatrix.sync.aligned.m8n8.x4.shared.b16 {%0,%1,%2,%3}, [%4];" \
        : "=r"((r)[0]), "=r"((r)[1]), "=r"((r)[2]), "=r"((r)[3]) : "r"(addr))

#define MMA_F16(c, a, b0v, b1v) \
    asm volatile("mma.sync.aligned.m16n8k16.row.col.f32.f16.f16.f32 " \
        "{%0,%1,%2,%3}, {%4,%5,%6,%7}, {%8,%9}, {%0,%1,%2,%3};" \
        : "+f"((c)[0]), "+f"((c)[1]), "+f"((c)[2]), "+f"((c)[3]) \
        : "r"((a)[0]), "r"((a)[1]), "r"((a)[2]), "r"((a)[3]), "r"(b0v), "r"(b1v))

__device__ __forceinline__ float fast_tanh(float x) {
    float r;
    asm("tanh.approx.f32 %0, %1;" : "=f"(r) : "f"(x));
    return r;
}

// ================= convert f32 -> f16 (enc + Wh in one launch) =============
#define ENC_N4   ((M_ / 4) * D_)      // 16,777,216 float4 units
#define ENC_BLKS 4096
#define WH_BLKS  256
__global__ __launch_bounds__(256)
void convert_kernel(const float* __restrict__ enc, const float* __restrict__ wh) {
    if (blockIdx.x < ENC_BLKS) {
        __half* dst = g_enc_h;
        const int stride = ENC_BLKS * 256;
        for (int i = blockIdx.x * 256 + threadIdx.x; i < ENC_N4; i += stride) {
            const float4 v = ((const float4*)enc)[i];
            __half2* d = (__half2*)dst + (size_t)i * 2;
            d[0] = __floats2half2_rn(v.x, v.y);
            d[1] = __floats2half2_rn(v.z, v.w);
        }
    } else {
        __half* dst = g_wh_h;
        const int n4 = (D_ / 4) * D_;
        const int stride = WH_BLKS * 256;
        for (int i = (blockIdx.x - ENC_BLKS) * 256 + threadIdx.x; i < n4; i += stride) {
            const float4 v = ((const float4*)wh)[i];
            __half2* d = (__half2*)dst + (size_t)i * 2;
            d[0] = __floats2half2_rn(v.x, v.y);
            d[1] = __floats2half2_rn(v.z, v.w);
        }
    }
}

// ================= score GEMM: BM=256 x BN=128, 512 thr, 4 stages ============
#define BM   256
#define BN   128
#define BK   64                     // fp16 elems = 128 bytes
#define STG  4
#define NKT  (D_ / BK)              // 16
#define SA_OFF(s) ((s) * 32768)                 // A: 4 x 32KB
#define SB_OFF(s) (131072 + (s) * 16384)        // B: 4 x 16KB
#define OFF_DF  196608
#define OFF_WC  (OFF_DF + 512)
#define OFF_V   (OFF_WC + 512)
#define OFF_CV  (OFF_V + 512)                   // 256 floats = 1024B
#define OFF_SBF (OFF_CV + 1024)                 // 256*4 floats = 4096B
#define SMEM_DYN (OFF_SBF + 4096)

__global__ __launch_bounds__(512, 1)
void score_gemm_kernel(const float* __restrict__ coverage,
                       const float* __restrict__ w_c,
                       const float* __restrict__ v) {
    extern __shared__ __align__(128) char smem[];
    const uint32_t sb = smem_u32(smem);
    const int tid = threadIdx.x, lane = tid & 31, wid = tid >> 5;
    const int wm = wid >> 2, wn = wid & 3;      // 4 x 4 warp grid
    const int n0 = blockIdx.x * BN;
    const int m0 = blockIdx.y * BM;

    const __half* A  = g_enc_h;
    const __half* Bw = g_wh_h;

    if (tid < 128) {
        const int e = n0 + tid;
        ((float*)(smem + OFF_DF))[tid] = g_dec_feat[(m0 >> 12) * D_ + e];
        ((float*)(smem + OFF_WC))[tid] = w_c[e];
        ((float*)(smem + OFF_V))[tid]  = v[e];
    }
    if (tid < 256)
        ((float*)(smem + OFF_CV))[tid] = coverage[m0 + tid];

    // ldmatrix per-lane geometry (warp tile 64 x 32)
    const int a_rowb = wm * 64 + (lane & 15);                       // + mt*16
    const int a_cofs = lane >> 4;
    const int b_rowb = wn * 32 + ((lane >> 4) << 3) + (lane & 7);   // + p*16
    const int b_cofs = (lane >> 3) & 1;

    float acc[4][4][4];
    #pragma unroll
    for (int i = 0; i < 4; i++)
        #pragma unroll
        for (int j = 0; j < 4; j++)
            #pragma unroll
            for (int k = 0; k < 4; k++) acc[i][j][k] = 0.f;

    // stage loader: A 4 cp.async + B 2 cp.async per thread (48KB per stage)
    auto load_stage = [&](int st, int kt) {
        #pragma unroll
        for (int it = 0; it < 4; it++) {
            const int idx = tid + it * 512;            // 0..2047
            const int row = idx >> 3, cb = idx & 7;
            const __half* srcA = A + (size_t)(m0 + row) * D_ + kt * BK + cb * 8;
            const uint32_t dstA = sb + SA_OFF(st) + row * 128 + ((cb ^ (row & 7)) << 4);
            CP_ASYNC16(dstA, srcA);
        }
        #pragma unroll
        for (int it = 0; it < 2; it++) {
            const int idx = tid + it * 512;            // 0..1023
            const int row = idx >> 3, cb = idx & 7;
            const __half* srcB = Bw + (size_t)(n0 + row) * D_ + kt * BK + cb * 8;
            const uint32_t dstB = sb + SB_OFF(st) + row * 128 + ((cb ^ (row & 7)) << 4);
            CP_ASYNC16(dstB, srcB);
        }
    };

    load_stage(0, 0); CP_COMMIT();
    load_stage(1, 1); CP_COMMIT();
    load_stage(2, 2); CP_COMMIT();

    for (int kt = 0; kt < NKT; kt++) {
        CP_WAIT2();
        __syncthreads();

        const int st = kt & 3;
        const uint32_t aB = sb + SA_OFF(st);
        const uint32_t bB = sb + SB_OFF(st);

        #pragma unroll
        for (int ks = 0; ks < 4; ks++) {     // 4 x k16 per BK=64
            uint32_t af[4][4], bf[2][4];
            #pragma unroll
            for (int mt = 0; mt < 4; mt++) {
                const int row = a_rowb + mt * 16;
                const int ch  = 2 * ks + a_cofs;
                LDSM4(af[mt], aB + row * 128 + ((ch ^ (row & 7)) << 4));
            }
            #pragma unroll
            for (int p = 0; p < 2; p++) {
                const int row = b_rowb + p * 16;
                const int ch  = 2 * ks + b_cofs;
                LDSM4(bf[p], bB + row * 128 + ((ch ^ (row & 7)) << 4));
            }
            #pragma unroll
            for (int mt = 0; mt < 4; mt++)
                #pragma unroll
                for (int nt = 0; nt < 4; nt++)
                    MMA_F16(acc[mt][nt], af[mt],
                            bf[nt >> 1][(nt & 1) * 2], bf[nt >> 1][(nt & 1) * 2 + 1]);

            // prefetch stage kt+3 into slot (kt+3)&3 = (kt-1)&3 (consumed at kt-1)
            if (ks == 0) {
                if (kt + 3 < NKT) load_stage((kt + 3) & 3, kt + 3);
                CP_COMMIT();
            }
        }
    }
    __syncthreads();

    // -------- fused epilogue: tanh.approx + v-dot -> per-row partial --------
    const float* sdf  = (const float*)(smem + OFF_DF);
    const float* swc  = (const float*)(smem + OFF_WC);
    const float* sv   = (const float*)(smem + OFF_V);
    const float* scov = (const float*)(smem + OFF_CV);
    float* sbuf = (float*)(smem + OFF_SBF);

    const int g = lane >> 2, tig = lane & 3;
    #pragma unroll
    for (int mt = 0; mt < 4; mt++) {
        #pragma unroll
        for (int h = 0; h < 2; h++) {
            const int rl = wm * 64 + mt * 16 + h * 8 + g;     // 0..255
            const float cov = scov[rl];
            float part = 0.f;
            #pragma unroll
            for (int nt = 0; nt < 4; nt++) {
                #pragma unroll
                for (int q = 0; q < 2; q++) {
                    const int cl = wn * 32 + nt * 8 + tig * 2 + q;
                    const float x = acc[mt][nt][h * 2 + q] + sdf[cl] + cov * swc[cl];
                    part = fmaf(sv[cl], fast_tanh(x), part);
                }
            }
            part += __shfl_down_sync(0xffffffffu, part, 1, 4);
            part += __shfl_down_sync(0xffffffffu, part, 2, 4);
            if (tig == 0) sbuf[rl * 4 + wn] = part;
        }
    }
    __syncthreads();
    if (tid < 256) {
        const float s = sbuf[tid * 4] + sbuf[tid * 4 + 1]
                      + sbuf[tid * 4 + 2] + sbuf[tid * 4 + 3];
        g_score_part[(size_t)blockIdx.x * M_ + m0 + tid] = s;
    }
}

// ================= kernel 1: dec_feat =================
__global__ __launch_bounds__(128)
void dec_feat_kernel(const float* __restrict__ dec,
                     const float* __restrict__ Ws,
                     const float* __restrict__ bs) {
    const int e = blockIdx.x;
    const int tid = threadIdx.x;
    const float* wrow = Ws + (size_t)e * D_;
    float w8[8];
    #pragma unroll
    for (int j = 0; j < 8; j++) w8[j] = wrow[j * 128 + tid];

    __shared__ float sred[4];
    const int lane = tid & 31, w = tid >> 5;
    const float be = bs[e];

    for (int b = 0; b < B_; b++) {
        const float* drow = dec + (size_t)b * D_;
        float a = 0.f;
        #pragma unroll
        for (int j = 0; j < 8; j++) a = fmaf(w8[j], drow[j * 128 + tid], a);
        #pragma unroll
        for (int off = 16; off > 0; off >>= 1)
            a += __shfl_down_sync(0xffffffffu, a, off);
        if (lane == 0) sred[w] = a;
        __syncthreads();
        if (tid == 0)
            g_dec_feat[b * D_ + e] = sred[0] + sred[1] + sred[2] + sred[3] + be;
        __syncthreads();
    }
}

// ================= kernel 3: softmax =================
__device__ __forceinline__ float block_reduce_1024(float val, bool is_max) {
    __shared__ float sh[32];
    __syncthreads();
    const int lane = threadIdx.x & 31, wid = threadIdx.x >> 5;
    #pragma unroll
    for (int off = 16; off > 0; off >>= 1) {
        float o = __shfl_down_sync(0xffffffffu, val, off);
        val = is_max ? fmaxf(val, o) : (val + o);
    }
    if (lane == 0) sh[wid] = val;
    __syncthreads();
    if (wid == 0) {
        val = sh[lane];
        #pragma unroll
        for (int off = 16; off > 0; off >>= 1) {
            float o = __shfl_down_sync(0xffffffffu, val, off);
            val = is_max ? fmaxf(val, o) : (val + o);
        }
        if (lane == 0) sh[0] = val;
    }
    __syncthreads();
    return sh[0];
}

__global__ __launch_bounds__(1024)
void softmax_kernel(const float* __restrict__ mask,
                    const float* __restrict__ coverage,
                    float* __restrict__ attn_out,
                    float* __restrict__ cov_out) {
    const int b = blockIdx.x;
    const int tid = threadIdx.x;

    float sc[4];
    #pragma unroll
    for (int i = 0; i < 4; i++) {
        const int idx = b * S_ + tid + i * 1024;
        float t = 0.f;
        #pragma unroll
        for (int p = 0; p < NBC_; p++) t += g_score_part[(size_t)p * M_ + idx];
        sc[i] = t;
    }
    float mx = fmaxf(fmaxf(sc[0], sc[1]), fmaxf(sc[2], sc[3]));
    mx = block_reduce_1024(mx, true);

    float e[4], lsum = 0.f;
    #pragma unroll
    for (int i = 0; i < 4; i++) { e[i] = expf(sc[i] - mx); lsum += e[i]; }
    const float tot = block_reduce_1024(lsum, false);

    float p[4], lsum2 = 0.f;
    #pragma unroll
    for (int i = 0; i < 4; i++) {
        const int s = tid + i * 1024;
        p[i] = (e[i] / tot) * mask[b * S_ + s];
        lsum2 += p[i];
    }
    const float tot2 = block_reduce_1024(lsum2, false);

    #pragma unroll
    for (int i = 0; i < 4; i++) {
        const int s = tid + i * 1024;
        const float a = p[i] / tot2;
        attn_out[b * S_ + s] = a;
        cov_out[b * S_ + s]  = coverage[b * S_ + s] + a;
    }
}

// ================= kernel 4/5: context (fp16 encoder mirror) =================
__global__ __launch_bounds__(256)
void ctx_part_kernel(const float* __restrict__ attn) {
    const int b  = blockIdx.x;
    const int sc = blockIdx.y;
    const int s0 = sc * 128;
    const uint2* ep = (const uint2*)(g_enc_h + ((size_t)b * S_ + s0) * D_) + threadIdx.x;
    const float* ap = attn + b * S_ + s0;
    float ax = 0.f, ay = 0.f, az = 0.f, aw = 0.f;
    #pragma unroll 4
    for (int s = 0; s < 128; s++) {
        const float a = ap[s];
        const uint2 e8 = ep[(size_t)s * 256];
        const float2 e0 = __half22float2(*(const __half2*)&e8.x);
        const float2 e1 = __half22float2(*(const __half2*)&e8.y);
        ax = fmaf(a, e0.x, ax);
        ay = fmaf(a, e0.y, ay);
        az = fmaf(a, e1.x, az);
        aw = fmaf(a, e1.y, aw);
    }
    float4 r = {ax, ay, az, aw};
    ((float4*)(g_ctx_part + ((size_t)sc * B_ + b) * D_))[threadIdx.x] = r;
}

__global__ void ctx_reduce_kernel(float* __restrict__ ctx_out) {
    const int idx = blockIdx.x * 256 + threadIdx.x;
    float a = 0.f;
    #pragma unroll
    for (int p = 0; p < 32; p++) a += g_ctx_part[(size_t)p * (B_ * D_) + idx];
    ctx_out[idx] = a;
}

// ================= launcher =================
extern "C" void kernel_launch(void* const* d_in, const int* in_sizes, int n_in,
                              void* d_out, int out_size) {
    const float* enc  = (const float*)d_in[0];
    const float* dec  = (const float*)d_in[1];
    const float* mask = (const float*)d_in[2];
    const float* cov  = (const float*)d_in[3];
    const float* Wh   = (const float*)d_in[4];
    const float* Ws   = (const float*)d_in[5];
    const float* bs   = (const float*)d_in[6];
    const float* wc   = (const float*)d_in[7];
    const float* v    = (const float*)d_in[8];

    float* out  = (float*)d_out;
    float* ctx  = out;
    float* attn = out + B_ * D_;
    float* covn = attn + B_ * S_;

    static bool attr_set = false;
    if (!attr_set) {
        cudaFuncSetAttribute(score_gemm_kernel,
                             cudaFuncAttributeMaxDynamicSharedMemorySize, SMEM_DYN);
        attr_set = true;
    }

    convert_kernel<<<ENC_BLKS + WH_BLKS, 256>>>(enc, Wh);
    dec_feat_kernel<<<D_, 128>>>(dec, Ws, bs);
    score_gemm_kernel<<<dim3(D_ / BN, M_ / BM), 512, SMEM_DYN>>>(cov, wc, v);
    softmax_kernel<<<B_, 1024>>>(mask, cov, attn, covn);
    ctx_part_kernel<<<dim3(B_, 32), 256>>>(attn);
    ctx_reduce_kernel<<<64, 256>>>(ctx);
}

// round 11
// speedup vs baseline: 1.0554x; 1.0554x over previous
#include <cuda_runtime.h>
#include <cuda_fp16.h>
#include <math.h>
#include <stdint.h>

// Problem constants
#define B_   16
#define S_   4096
#define D_   1024
#define M_   (B_ * S_)
#define NBC_ 8               // n partial blocks (1024 / 128)

// ---------------- device scratch ----------------
__device__ float g_dec_feat[B_ * D_];
__device__ float g_score_part[NBC_ * M_];
__device__ float g_scores[M_];
__device__ float g_cstat[B_ * 8 * 2];     // per-chunk (max, scaled-sum)
__device__ float g_bstat[B_ * 2];         // per-batch (max, T)
__device__ float g_ctx_part[32 * B_ * D_];
__device__ __align__(16) __half g_enc_h[(size_t)M_ * D_];
__device__ __align__(16) __half g_wh_h[(size_t)D_ * D_];

// ================= PTX helpers (plain sm_100-safe) =================
__device__ __forceinline__ uint32_t smem_u32(const void* p) {
    uint32_t a;
    asm("{ .reg .u64 t; cvta.to.shared.u64 t, %1; cvt.u32.u64 %0, t; }" : "=r"(a) : "l"(p));
    return a;
}

#define CP_ASYNC16(dst, src) \
    asm volatile("cp.async.cg.shared.global [%0], [%1], 16;" :: "r"(dst), "l"(src) : "memory")
#define CP_COMMIT() asm volatile("cp.async.commit_group;" ::: "memory")
#define CP_WAIT1()  asm volatile("cp.async.wait_group 1;" ::: "memory")

#define LDSM4(r, addr) \
    asm volatile("ldmatrix.sync.aligned.m8n8.x4.shared.b16 {%0,%1,%2,%3}, [%4];" \
        : "=r"((r)[0]), "=r"((r)[1]), "=r"((r)[2]), "=r"((r)[3]) : "r"(addr))

#define MMA_F16(c, a, b0v, b1v) \
    asm volatile("mma.sync.aligned.m16n8k16.row.col.f32.f16.f16.f32 " \
        "{%0,%1,%2,%3}, {%4,%5,%6,%7}, {%8,%9}, {%0,%1,%2,%3};" \
        : "+f"((c)[0]), "+f"((c)[1]), "+f"((c)[2]), "+f"((c)[3]) \
        : "r"((a)[0]), "r"((a)[1]), "r"((a)[2]), "r"((a)[3]), "r"(b0v), "r"(b1v))

__device__ __forceinline__ float fast_tanh(float x) {
    float r;
    asm("tanh.approx.f32 %0, %1;" : "=f"(r) : "f"(x));
    return r;
}

// ===== convert f32->f16 (enc + Wh) AND dec_feat in one launch ==============
#define ENC_N4   ((M_ / 4) * D_)
#define ENC_BLKS 4096
#define WH_BLKS  256
#define DF_BLKS  1024
__global__ __launch_bounds__(256)
void prep_kernel(const float* __restrict__ enc, const float* __restrict__ wh,
                 const float* __restrict__ dec, const float* __restrict__ Ws,
                 const float* __restrict__ bs) {
    if (blockIdx.x < ENC_BLKS) {
        __half* dst = g_enc_h;
        const int stride = ENC_BLKS * 256;
        for (int i = blockIdx.x * 256 + threadIdx.x; i < ENC_N4; i += stride) {
            const float4 v = ((const float4*)enc)[i];
            __half2* d = (__half2*)dst + (size_t)i * 2;
            d[0] = __floats2half2_rn(v.x, v.y);
            d[1] = __floats2half2_rn(v.z, v.w);
        }
    } else if (blockIdx.x < ENC_BLKS + WH_BLKS) {
        __half* dst = g_wh_h;
        const int n4 = (D_ / 4) * D_;
        const int stride = WH_BLKS * 256;
        for (int i = (blockIdx.x - ENC_BLKS) * 256 + threadIdx.x; i < n4; i += stride) {
            const float4 v = ((const float4*)wh)[i];
            __half2* d = (__half2*)dst + (size_t)i * 2;
            d[0] = __floats2half2_rn(v.x, v.y);
            d[1] = __floats2half2_rn(v.z, v.w);
        }
    } else {
        // dec_feat: one block per e (256 threads)
        const int e = blockIdx.x - ENC_BLKS - WH_BLKS;
        const int tid = threadIdx.x;
        const float* wrow = Ws + (size_t)e * D_;
        float w4[4];
        #pragma unroll
        for (int j = 0; j < 4; j++) w4[j] = wrow[j * 256 + tid];

        __shared__ float sred[8];
        const int lane = tid & 31, w = tid >> 5;
        const float be = bs[e];

        for (int b = 0; b < B_; b++) {
            const float* drow = dec + (size_t)b * D_;
            float a = 0.f;
            #pragma unroll
            for (int j = 0; j < 4; j++) a = fmaf(w4[j], drow[j * 256 + tid], a);
            #pragma unroll
            for (int off = 16; off > 0; off >>= 1)
                a += __shfl_down_sync(0xffffffffu, a, off);
            if (lane == 0) sred[w] = a;
            __syncthreads();
            if (tid == 0) {
                float t = 0.f;
                #pragma unroll
                for (int k = 0; k < 8; k++) t += sred[k];
                g_dec_feat[b * D_ + e] = t + be;
            }
            __syncthreads();
        }
    }
}

// ================= score GEMM (R6 config: 128x128, 3 stages) =================
#define BM   128
#define BN   128
#define BK   64
#define STG  3
#define NKT  (D_ / BK)
#define SA_OFF(s) ((s) * 16384)
#define SB_OFF(s) (49152 + (s) * 16384)
#define OFF_DF  98304
#define OFF_WC  (OFF_DF + 512)
#define OFF_V   (OFF_WC + 512)
#define OFF_CV  (OFF_V + 512)
#define OFF_SBF (OFF_CV + 512)
#define SMEM_DYN (OFF_SBF + 2048)

__global__ __launch_bounds__(256, 2)
void score_gemm_kernel(const float* __restrict__ coverage,
                       const float* __restrict__ w_c,
                       const float* __restrict__ v) {
    extern __shared__ __align__(128) char smem[];
    const uint32_t sb = smem_u32(smem);
    const int tid = threadIdx.x, lane = tid & 31, wid = tid >> 5;
    const int wm = wid >> 2, wn = wid & 3;
    const int n0 = blockIdx.x * BN;
    const int m0 = blockIdx.y * BM;

    const __half* A  = g_enc_h;
    const __half* Bw = g_wh_h;

    if (tid < 128) {
        const int e = n0 + tid;
        ((float*)(smem + OFF_DF))[tid] = g_dec_feat[(m0 >> 12) * D_ + e];
        ((float*)(smem + OFF_WC))[tid] = w_c[e];
        ((float*)(smem + OFF_V))[tid]  = v[e];
        ((float*)(smem + OFF_CV))[tid] = coverage[m0 + tid];
    }

    const int a_rowb = wm * 64 + (lane & 15);
    const int a_cofs = lane >> 4;
    const int b_rowb = wn * 32 + ((lane >> 4) << 3) + (lane & 7);
    const int b_cofs = (lane >> 3) & 1;

    float acc[4][4][4];
    #pragma unroll
    for (int i = 0; i < 4; i++)
        #pragma unroll
        for (int j = 0; j < 4; j++)
            #pragma unroll
            for (int k = 0; k < 4; k++) acc[i][j][k] = 0.f;

    auto load_stage = [&](int st, int kt) {
        #pragma unroll
        for (int it = 0; it < 4; it++) {
            const int idx = tid + it * 256;
            const int row = idx >> 3, cb = idx & 7;
            const __half* srcA = A + (size_t)(m0 + row) * D_ + kt * BK + cb * 8;
            const uint32_t dstA = sb + SA_OFF(st) + row * 128 + ((cb ^ (row & 7)) << 4);
            CP_ASYNC16(dstA, srcA);
        }
        #pragma unroll
        for (int it = 0; it < 4; it++) {
            const int idx = tid + it * 256;
            const int row = idx >> 3, cb = idx & 7;
            const __half* srcB = Bw + (size_t)(n0 + row) * D_ + kt * BK + cb * 8;
            const uint32_t dstB = sb + SB_OFF(st) + row * 128 + ((cb ^ (row & 7)) << 4);
            CP_ASYNC16(dstB, srcB);
        }
    };

    load_stage(0, 0); CP_COMMIT();
    load_stage(1, 1); CP_COMMIT();

    for (int kt = 0; kt < NKT; kt++) {
        CP_WAIT1();
        __syncthreads();
        if (kt + 2 < NKT) load_stage((kt + 2) % STG, kt + 2);
        CP_COMMIT();

        const int st = kt % STG;
        const uint32_t aB = sb + SA_OFF(st);
        const uint32_t bB = sb + SB_OFF(st);

        #pragma unroll
        for (int ks = 0; ks < 4; ks++) {
            uint32_t af[4][4], bf[2][4];
            #pragma unroll
            for (int mt = 0; mt < 4; mt++) {
                const int row = a_rowb + mt * 16;
                const int ch  = 2 * ks + a_cofs;
                LDSM4(af[mt], aB + row * 128 + ((ch ^ (row & 7)) << 4));
            }
            #pragma unroll
            for (int p = 0; p < 2; p++) {
                const int row = b_rowb + p * 16;
                const int ch  = 2 * ks + b_cofs;
                LDSM4(bf[p], bB + row * 128 + ((ch ^ (row & 7)) << 4));
            }
            #pragma unroll
            for (int mt = 0; mt < 4; mt++)
                #pragma unroll
                for (int nt = 0; nt < 4; nt++)
                    MMA_F16(acc[mt][nt], af[mt],
                            bf[nt >> 1][(nt & 1) * 2], bf[nt >> 1][(nt & 1) * 2 + 1]);
        }
    }
    __syncthreads();

    const float* sdf  = (const float*)(smem + OFF_DF);
    const float* swc  = (const float*)(smem + OFF_WC);
    const float* sv   = (const float*)(smem + OFF_V);
    const float* scov = (const float*)(smem + OFF_CV);
    float* sbuf = (float*)(smem + OFF_SBF);

    const int g = lane >> 2, tig = lane & 3;
    #pragma unroll
    for (int mt = 0; mt < 4; mt++) {
        #pragma unroll
        for (int h = 0; h < 2; h++) {
            const int rl = wm * 64 + mt * 16 + h * 8 + g;
            const float cov = scov[rl];
            float part = 0.f;
            #pragma unroll
            for (int nt = 0; nt < 4; nt++) {
                #pragma unroll
                for (int q = 0; q < 2; q++) {
                    const int cl = wn * 32 + nt * 8 + tig * 2 + q;
                    const float x = acc[mt][nt][h * 2 + q] + sdf[cl] + cov * swc[cl];
                    part = fmaf(sv[cl], fast_tanh(x), part);
                }
            }
            part += __shfl_down_sync(0xffffffffu, part, 1, 4);
            part += __shfl_down_sync(0xffffffffu, part, 2, 4);
            if (tig == 0) sbuf[rl * 4 + wn] = part;
        }
    }
    __syncthreads();
    if (tid < 128) {
        const float s = sbuf[tid * 4] + sbuf[tid * 4 + 1]
                      + sbuf[tid * 4 + 2] + sbuf[tid * 4 + 3];
        g_score_part[(size_t)blockIdx.x * M_ + m0 + tid] = s;
    }
}

// ===== stats pass 1: sum partials -> scores; per-512-chunk (max, scaled sum)
__global__ __launch_bounds__(512)
void stats1_kernel(const float* __restrict__ mask) {
    const int b = blockIdx.x, c = blockIdx.y;
    const int tid = threadIdx.x;
    const int idx = b * S_ + c * 512 + tid;

    float sc = 0.f;
    #pragma unroll
    for (int p = 0; p < NBC_; p++) sc += g_score_part[(size_t)p * M_ + idx];
    g_scores[idx] = sc;

    __shared__ float sh[16];
    const int lane = tid & 31, w = tid >> 5;
    // chunk max
    float mx = sc;
    #pragma unroll
    for (int off = 16; off > 0; off >>= 1)
        mx = fmaxf(mx, __shfl_down_sync(0xffffffffu, mx, off));
    if (lane == 0) sh[w] = mx;
    __syncthreads();
    if (tid < 16) {
        float t = sh[tid];
        #pragma unroll
        for (int off = 8; off > 0; off >>= 1)
            t = fmaxf(t, __shfl_down_sync(0xffffu, t, off, 16));
        if (tid == 0) sh[0] = t;
    }
    __syncthreads();
    mx = sh[0];
    __syncthreads();

    // chunk masked exp-sum
    float e = expf(sc - mx) * mask[idx];
    #pragma unroll
    for (int off = 16; off > 0; off >>= 1)
        e += __shfl_down_sync(0xffffffffu, e, off);
    if (lane == 0) sh[w] = e;
    __syncthreads();
    if (tid < 16) {
        float t = sh[tid];
        #pragma unroll
        for (int off = 8; off > 0; off >>= 1)
            t += __shfl_down_sync(0xffffu, t, off, 16);
        if (tid == 0) {
            g_cstat[(b * 8 + c) * 2]     = mx;
            g_cstat[(b * 8 + c) * 2 + 1] = t;
        }
    }
}

// ===== stats pass 2: merge 8 chunks -> per-batch (M, T) =====
__global__ void stats2_kernel() {
    const int b = threadIdx.x;
    if (b >= B_) return;
    float M = -1e30f;
    #pragma unroll
    for (int c = 0; c < 8; c++) M = fmaxf(M, g_cstat[(b * 8 + c) * 2]);
    float T = 0.f;
    #pragma unroll
    for (int c = 0; c < 8; c++)
        T += g_cstat[(b * 8 + c) * 2 + 1] * expf(g_cstat[(b * 8 + c) * 2] - M);
    g_bstat[b * 2]     = M;
    g_bstat[b * 2 + 1] = T;
}

// ===== fused attn + coverage + context partials =====
__global__ __launch_bounds__(256)
void ctx_part_kernel(const float* __restrict__ mask,
                     const float* __restrict__ coverage,
                     float* __restrict__ attn_out,
                     float* __restrict__ cov_out) {
    const int b  = blockIdx.x;
    const int sc = blockIdx.y;
    const int s0 = sc * 128;
    const int tid = threadIdx.x;

    __shared__ float attn_sm[128];
    const float M = g_bstat[b * 2];
    const float T = g_bstat[b * 2 + 1];
    if (tid < 128) {
        const int si = b * S_ + s0 + tid;
        const float a = expf(g_scores[si] - M) * mask[si] / T;
        attn_sm[tid] = a;
        attn_out[si] = a;
        cov_out[si]  = coverage[si] + a;
    }
    __syncthreads();

    const uint2* ep = (const uint2*)(g_enc_h + ((size_t)b * S_ + s0) * D_) + tid;
    float ax = 0.f, ay = 0.f, az = 0.f, aw = 0.f;
    #pragma unroll 4
    for (int s = 0; s < 128; s++) {
        const float a = attn_sm[s];
        const uint2 e8 = ep[(size_t)s * 256];
        const float2 e0 = __half22float2(*(const __half2*)&e8.x);
        const float2 e1 = __half22float2(*(const __half2*)&e8.y);
        ax = fmaf(a, e0.x, ax);
        ay = fmaf(a, e0.y, ay);
        az = fmaf(a, e1.x, az);
        aw = fmaf(a, e1.y, aw);
    }
    float4 r = {ax, ay, az, aw};
    ((float4*)(g_ctx_part + ((size_t)sc * B_ + b) * D_))[tid] = r;
}

__global__ void ctx_reduce_kernel(float* __restrict__ ctx_out) {
    const int idx = blockIdx.x * 256 + threadIdx.x;
    float a = 0.f;
    #pragma unroll
    for (int p = 0; p < 32; p++) a += g_ctx_part[(size_t)p * (B_ * D_) + idx];
    ctx_out[idx] = a;
}

// ================= launcher =================
extern "C" void kernel_launch(void* const* d_in, const int* in_sizes, int n_in,
                              void* d_out, int out_size) {
    const float* enc  = (const float*)d_in[0];
    const float* dec  = (const float*)d_in[1];
    const float* mask = (const float*)d_in[2];
    const float* cov  = (const float*)d_in[3];
    const float* Wh   = (const float*)d_in[4];
    const float* Ws   = (const float*)d_in[5];
    const float* bs   = (const float*)d_in[6];
    const float* wc   = (const float*)d_in[7];
    const float* v    = (const float*)d_in[8];

    float* out  = (float*)d_out;
    float* ctx  = out;
    float* attn = out + B_ * D_;
    float* covn = attn + B_ * S_;

    static bool attr_set = false;
    if (!attr_set) {
        cudaFuncSetAttribute(score_gemm_kernel,
                             cudaFuncAttributeMaxDynamicSharedMemorySize, SMEM_DYN);
        attr_set = true;
    }

    prep_kernel<<<ENC_BLKS + WH_BLKS + DF_BLKS, 256>>>(enc, Wh, dec, Ws, bs);
    score_gemm_kernel<<<dim3(D_ / BN, M_ / BM), 256, SMEM_DYN>>>(cov, wc, v);
    stats1_kernel<<<dim3(B_, 8), 512>>>(mask);
    stats2_kernel<<<1, 32>>>();
    ctx_part_kernel<<<dim3(B_, 32), 256>>>(mask, cov, attn, covn);
    ctx_reduce_kernel<<<64, 256>>>(ctx);
}

// round 13
// speedup vs baseline: 1.0612x; 1.0055x over previous
#include <cuda_runtime.h>
#include <cuda_fp16.h>
#include <math.h>
#include <stdint.h>

// Problem constants
#define B_   16
#define S_   4096
#define D_   1024
#define M_   (B_ * S_)
#define NBC_ 8               // n partial blocks (1024 / 128)

// ---------------- device scratch ----------------
__device__ float g_dec_feat[B_ * D_];
__device__ float g_score_part[NBC_ * M_];
__device__ float g_escore[M_];            // exp(s - M_chunk) * mask
__device__ float g_cstat[B_ * 8 * 2];     // per-chunk (max, masked exp-sum)
__device__ float g_ctx_part[32 * B_ * D_];
__device__ __align__(16) __half g_enc_h[(size_t)M_ * D_];
__device__ __align__(16) __half g_wh_h[(size_t)D_ * D_];

// ================= PTX helpers (plain sm_100-safe) =================
__device__ __forceinline__ uint32_t smem_u32(const void* p) {
    uint32_t a;
    asm("{ .reg .u64 t; cvta.to.shared.u64 t, %1; cvt.u32.u64 %0, t; }" : "=r"(a) : "l"(p));
    return a;
}

#define CP_ASYNC16(dst, src) \
    asm volatile("cp.async.cg.shared.global [%0], [%1], 16;" :: "r"(dst), "l"(src) : "memory")
#define CP_COMMIT() asm volatile("cp.async.commit_group;" ::: "memory")
#define CP_WAIT1()  asm volatile("cp.async.wait_group 1;" ::: "memory")

#define LDSM4(r, addr) \
    asm volatile("ldmatrix.sync.aligned.m8n8.x4.shared.b16 {%0,%1,%2,%3}, [%4];" \
        : "=r"((r)[0]), "=r"((r)[1]), "=r"((r)[2]), "=r"((r)[3]) : "r"(addr))

#define MMA_F16(c, a, b0v, b1v) \
    asm volatile("mma.sync.aligned.m16n8k16.row.col.f32.f16.f16.f32 " \
        "{%0,%1,%2,%3}, {%4,%5,%6,%7}, {%8,%9}, {%0,%1,%2,%3};" \
        : "+f"((c)[0]), "+f"((c)[1]), "+f"((c)[2]), "+f"((c)[3]) \
        : "r"((a)[0]), "r"((a)[1]), "r"((a)[2]), "r"((a)[3]), "r"(b0v), "r"(b1v))

__device__ __forceinline__ float fast_tanh(float x) {
    float r;
    asm("tanh.approx.f32 %0, %1;" : "=f"(r) : "f"(x));
    return r;
}

// ===== prep: f32->f16 (enc + Wh) AND dec_feat in one launch ==============
#define ENC_N4   ((M_ / 4) * D_)
#define ENC_BLKS 4096
#define WH_BLKS  256
#define DF_BLKS  1024
__global__ __launch_bounds__(256)
void prep_kernel(const float* __restrict__ enc, const float* __restrict__ wh,
                 const float* __restrict__ dec, const float* __restrict__ Ws,
                 const float* __restrict__ bs) {
    if (blockIdx.x < ENC_BLKS) {
        __half* dst = g_enc_h;
        const int stride = ENC_BLKS * 256;
        for (int i = blockIdx.x * 256 + threadIdx.x; i < ENC_N4; i += stride) {
            const float4 v = ((const float4*)enc)[i];
            __half2* d = (__half2*)dst + (size_t)i * 2;
            d[0] = __floats2half2_rn(v.x, v.y);
            d[1] = __floats2half2_rn(v.z, v.w);
        }
    } else if (blockIdx.x < ENC_BLKS + WH_BLKS) {
        __half* dst = g_wh_h;
        const int n4 = (D_ / 4) * D_;
        const int stride = WH_BLKS * 256;
        for (int i = (blockIdx.x - ENC_BLKS) * 256 + threadIdx.x; i < n4; i += stride) {
            const float4 v = ((const float4*)wh)[i];
            __half2* d = (__half2*)dst + (size_t)i * 2;
            d[0] = __floats2half2_rn(v.x, v.y);
            d[1] = __floats2half2_rn(v.z, v.w);
        }
    } else {
        // dec_feat: one block per e (256 threads)
        const int e = blockIdx.x - ENC_BLKS - WH_BLKS;
        const int tid = threadIdx.x;
        const float* wrow = Ws + (size_t)e * D_;
        float w4[4];
        #pragma unroll
        for (int j = 0; j < 4; j++) w4[j] = wrow[j * 256 + tid];

        __shared__ float sred[8];
        const int lane = tid & 31, w = tid >> 5;
        const float be = bs[e];

        for (int b = 0; b < B_; b++) {
            const float* drow = dec + (size_t)b * D_;
            float a = 0.f;
            #pragma unroll
            for (int j = 0; j < 4; j++) a = fmaf(w4[j], drow[j * 256 + tid], a);
            #pragma unroll
            for (int off = 16; off > 0; off >>= 1)
                a += __shfl_down_sync(0xffffffffu, a, off);
            if (lane == 0) sred[w] = a;
            __syncthreads();
            if (tid == 0) {
                float t = 0.f;
                #pragma unroll
                for (int k = 0; k < 8; k++) t += sred[k];
                g_dec_feat[b * D_ + e] = t + be;
            }
            __syncthreads();
        }
    }
}

// ================= score GEMM (128x128, 3 stages, 2 CTA/SM) =================
#define BM   128
#define BN   128
#define BK   64
#define STG  3
#define NKT  (D_ / BK)
#define SA_OFF(s) ((s) * 16384)
#define SB_OFF(s) (49152 + (s) * 16384)
#define OFF_DF  98304
#define OFF_WC  (OFF_DF + 512)
#define OFF_V   (OFF_WC + 512)
#define OFF_CV  (OFF_V + 512)
#define OFF_SBF (OFF_CV + 512)
#define SMEM_DYN (OFF_SBF + 2048)

__global__ __launch_bounds__(256, 2)
void score_gemm_kernel(const float* __restrict__ coverage,
                       const float* __restrict__ w_c,
                       const float* __restrict__ v) {
    extern __shared__ __align__(128) char smem[];
    const uint32_t sb = smem_u32(smem);
    const int tid = threadIdx.x, lane = tid & 31, wid = tid >> 5;
    const int wm = wid >> 2, wn = wid & 3;
    const int n0 = blockIdx.x * BN;
    const int m0 = blockIdx.y * BM;

    const __half* A  = g_enc_h;
    const __half* Bw = g_wh_h;

    if (tid < 128) {
        const int e = n0 + tid;
        ((float*)(smem + OFF_DF))[tid] = g_dec_feat[(m0 >> 12) * D_ + e];
        ((float*)(smem + OFF_WC))[tid] = w_c[e];
        ((float*)(smem + OFF_V))[tid]  = v[e];
        ((float*)(smem + OFF_CV))[tid] = coverage[m0 + tid];
    }

    const int a_rowb = wm * 64 + (lane & 15);
    const int a_cofs = lane >> 4;
    const int b_rowb = wn * 32 + ((lane >> 4) << 3) + (lane & 7);
    const int b_cofs = (lane >> 3) & 1;

    float acc[4][4][4];
    #pragma unroll
    for (int i = 0; i < 4; i++)
        #pragma unroll
        for (int j = 0; j < 4; j++)
            #pragma unroll
            for (int k = 0; k < 4; k++) acc[i][j][k] = 0.f;

    auto load_stage = [&](int st, int kt) {
        #pragma unroll
        for (int it = 0; it < 4; it++) {
            const int idx = tid + it * 256;
            const int row = idx >> 3, cb = idx & 7;
            const __half* srcA = A + (size_t)(m0 + row) * D_ + kt * BK + cb * 8;
            const uint32_t dstA = sb + SA_OFF(st) + row * 128 + ((cb ^ (row & 7)) << 4);
            CP_ASYNC16(dstA, srcA);
        }
        #pragma unroll
        for (int it = 0; it < 4; it++) {
            const int idx = tid + it * 256;
            const int row = idx >> 3, cb = idx & 7;
            const __half* srcB = Bw + (size_t)(n0 + row) * D_ + kt * BK + cb * 8;
            const uint32_t dstB = sb + SB_OFF(st) + row * 128 + ((cb ^ (row & 7)) << 4);
            CP_ASYNC16(dstB, srcB);
        }
    };

    load_stage(0, 0); CP_COMMIT();
    load_stage(1, 1); CP_COMMIT();

    for (int kt = 0; kt < NKT; kt++) {
        CP_WAIT1();
        __syncthreads();
        if (kt + 2 < NKT) load_stage((kt + 2) % STG, kt + 2);
        CP_COMMIT();

        const int st = kt % STG;
        const uint32_t aB = sb + SA_OFF(st);
        const uint32_t bB = sb + SB_OFF(st);

        #pragma unroll
        for (int ks = 0; ks < 4; ks++) {
            uint32_t af[4][4], bf[2][4];
            #pragma unroll
            for (int mt = 0; mt < 4; mt++) {
                const int row = a_rowb + mt * 16;
                const int ch  = 2 * ks + a_cofs;
                LDSM4(af[mt], aB + row * 128 + ((ch ^ (row & 7)) << 4));
            }
            #pragma unroll
            for (int p = 0; p < 2; p++) {
                const int row = b_rowb + p * 16;
                const int ch  = 2 * ks + b_cofs;
                LDSM4(bf[p], bB + row * 128 + ((ch ^ (row & 7)) << 4));
            }
            #pragma unroll
            for (int mt = 0; mt < 4; mt++)
                #pragma unroll
                for (int nt = 0; nt < 4; nt++)
                    MMA_F16(acc[mt][nt], af[mt],
                            bf[nt >> 1][(nt & 1) * 2], bf[nt >> 1][(nt & 1) * 2 + 1]);
        }
    }
    __syncthreads();

    const float* sdf  = (const float*)(smem + OFF_DF);
    const float* swc  = (const float*)(smem + OFF_WC);
    const float* sv   = (const float*)(smem + OFF_V);
    const float* scov = (const float*)(smem + OFF_CV);
    float* sbuf = (float*)(smem + OFF_SBF);

    const int g = lane >> 2, tig = lane & 3;
    #pragma unroll
    for (int mt = 0; mt < 4; mt++) {
        #pragma unroll
        for (int h = 0; h < 2; h++) {
            const int rl = wm * 64 + mt * 16 + h * 8 + g;
            const float cov = scov[rl];
            float part = 0.f;
            #pragma unroll
            for (int nt = 0; nt < 4; nt++) {
                #pragma unroll
                for (int q = 0; q < 2; q++) {
                    const int cl = wn * 32 + nt * 8 + tig * 2 + q;
                    const float x = acc[mt][nt][h * 2 + q] + sdf[cl] + cov * swc[cl];
                    part = fmaf(sv[cl], fast_tanh(x), part);
                }
            }
            part += __shfl_down_sync(0xffffffffu, part, 1, 4);
            part += __shfl_down_sync(0xffffffffu, part, 2, 4);
            if (tig == 0) sbuf[rl * 4 + wn] = part;
        }
    }
    __syncthreads();
    if (tid < 128) {
        const float s = sbuf[tid * 4] + sbuf[tid * 4 + 1]
                      + sbuf[tid * 4 + 2] + sbuf[tid * 4 + 3];
        g_score_part[(size_t)blockIdx.x * M_ + m0 + tid] = s;
    }
}

// ===== stats1: sum partials; store masked exp; per-512-chunk (max, sum) =====
__global__ __launch_bounds__(512)
void stats1_kernel(const float* __restrict__ mask) {
    const int b = blockIdx.x, c = blockIdx.y;
    const int tid = threadIdx.x;
    const int idx = b * S_ + c * 512 + tid;

    float sc = 0.f;
    #pragma unroll
    for (int p = 0; p < NBC_; p++) sc += g_score_part[(size_t)p * M_ + idx];

    __shared__ float sh[16];
    const int lane = tid & 31, w = tid >> 5;
    // chunk max
    float mx = sc;
    #pragma unroll
    for (int off = 16; off > 0; off >>= 1)
        mx = fmaxf(mx, __shfl_down_sync(0xffffffffu, mx, off));
    if (lane == 0) sh[w] = mx;
    __syncthreads();
    if (tid < 16) {
        float t = sh[tid];
        #pragma unroll
        for (int off = 8; off > 0; off >>= 1)
            t = fmaxf(t, __shfl_down_sync(0xffffu, t, off, 16));
        if (tid == 0) sh[0] = t;
    }
    __syncthreads();
    mx = sh[0];
    __syncthreads();

    // masked exp, stored for ctx pass
    float e = expf(sc - mx) * mask[idx];
    g_escore[idx] = e;

    // chunk masked exp-sum
    #pragma unroll
    for (int off = 16; off > 0; off >>= 1)
        e += __shfl_down_sync(0xffffffffu, e, off);
    if (lane == 0) sh[w] = e;
    __syncthreads();
    if (tid < 16) {
        float t = sh[tid];
        #pragma unroll
        for (int off = 8; off > 0; off >>= 1)
            t += __shfl_down_sync(0xffffu, t, off, 16);
        if (tid == 0) {
            g_cstat[(b * 8 + c) * 2]     = mx;
            g_cstat[(b * 8 + c) * 2 + 1] = t;
        }
    }
}

// ===== fused batch-stat merge + attn + coverage + context partials =====
__global__ __launch_bounds__(256)
void ctx_part_kernel(const float* __restrict__ coverage,
                     float* __restrict__ attn_out,
                     float* __restrict__ cov_out) {
    const int b  = blockIdx.x;
    const int sc = blockIdx.y;            // 0..31 (128-s chunks)
    const int s0 = sc * 128;
    const int tid = threadIdx.x;

    __shared__ float attn_sm[128];
    __shared__ float s_scale;

    if (tid == 0) {
        // merge this batch's 8 chunk stats -> (M, T), then per-chunk scale
        float Mx = -1e30f;
        #pragma unroll
        for (int c = 0; c < 8; c++) Mx = fmaxf(Mx, g_cstat[(b * 8 + c) * 2]);
        float T = 0.f;
        #pragma unroll
        for (int c = 0; c < 8; c++)
            T += g_cstat[(b * 8 + c) * 2 + 1] * expf(g_cstat[(b * 8 + c) * 2] - Mx);
        const int myc = sc >> 2;          // 512-chunk containing this 128-chunk
        s_scale = expf(g_cstat[(b * 8 + myc) * 2] - Mx) / T;
    }
    __syncthreads();

    const float scale = s_scale;
    if (tid < 128) {
        const int si = b * S_ + s0 + tid;
        const float a = g_escore[si] * scale;
        attn_sm[tid] = a;
        attn_out[si] = a;
        cov_out[si]  = coverage[si] + a;
    }
    __syncthreads();

    const uint2* ep = (const uint2*)(g_enc_h + ((size_t)b * S_ + s0) * D_) + tid;
    float ax = 0.f, ay = 0.f, az = 0.f, aw = 0.f;
    #pragma unroll 4
    for (int s = 0; s < 128; s++) {
        const float a = attn_sm[s];
        const uint2 e8 = ep[(size_t)s * 256];
        const float2 e0 = __half22float2(*(const __half2*)&e8.x);
        const float2 e1 = __half22float2(*(const __half2*)&e8.y);
        ax = fmaf(a, e0.x, ax);
        ay = fmaf(a, e0.y, ay);
        az = fmaf(a, e1.x, az);
        aw = fmaf(a, e1.y, aw);
    }
    float4 r = {ax, ay, az, aw};
    ((float4*)(g_ctx_part + ((size_t)sc * B_ + b) * D_))[tid] = r;
}

__global__ void ctx_reduce_kernel(float* __restrict__ ctx_out) {
    const int idx = blockIdx.x * 256 + threadIdx.x;
    float a = 0.f;
    #pragma unroll
    for (int p = 0; p < 32; p++) a += g_ctx_part[(size_t)p * (B_ * D_) + idx];
    ctx_out[idx] = a;
}

// ================= launcher =================
extern "C" void kernel_launch(void* const* d_in, const int* in_sizes, int n_in,
                              void* d_out, int out_size) {
    const float* enc  = (const float*)d_in[0];
    const float* dec  = (const float*)d_in[1];
    const float* mask = (const float*)d_in[2];
    const float* cov  = (const float*)d_in[3];
    const float* Wh   = (const float*)d_in[4];
    const float* Ws   = (const float*)d_in[5];
    const float* bs   = (const float*)d_in[6];
    const float* wc   = (const float*)d_in[7];
    const float* v    = (const float*)d_in[8];

    float* out  = (float*)d_out;
    float* ctx  = out;
    float* attn = out + B_ * D_;
    float* covn = attn + B_ * S_;

    static bool attr_set = false;
    if (!attr_set) {
        cudaFuncSetAttribute(score_gemm_kernel,
                             cudaFuncAttributeMaxDynamicSharedMemorySize, SMEM_DYN);
        attr_set = true;
    }

    prep_kernel<<<ENC_BLKS + WH_BLKS + DF_BLKS, 256>>>(enc, Wh, dec, Ws, bs);
    score_gemm_kernel<<<dim3(D_ / BN, M_ / BM), 256, SMEM_DYN>>>(cov, wc, v);
    stats1_kernel<<<dim3(B_, 8), 512>>>(mask);
    ctx_part_kernel<<<dim3(B_, 32), 256>>>(cov, attn, covn);
    ctx_reduce_kernel<<<64, 256>>>(ctx);
}

// round 14
// speedup vs baseline: 1.0645x; 1.0032x over previous
#include <cuda_runtime.h>
#include <cuda_fp16.h>
#include <math.h>
#include <stdint.h>

// Problem constants
#define B_   16
#define S_   4096
#define D_   1024
#define M_   (B_ * S_)
#define NBC_ 8               // n partial blocks (1024 / 128)

// ---------------- device scratch ----------------
__device__ float g_dec_feat[B_ * D_];
__device__ float g_score_part[NBC_ * M_];
__device__ float g_escore[M_];            // exp(s - M_chunk) * mask
__device__ float g_cstat[B_ * 8 * 2];     // per-chunk (max, masked exp-sum)
__device__ float g_ctx_part[64 * B_ * D_];
__device__ __align__(16) __half g_enc_h[(size_t)M_ * D_];
__device__ __align__(16) __half g_wh_h[(size_t)D_ * D_];

// ================= PTX helpers (plain sm_100-safe) =================
__device__ __forceinline__ uint32_t smem_u32(const void* p) {
    uint32_t a;
    asm("{ .reg .u64 t; cvta.to.shared.u64 t, %1; cvt.u32.u64 %0, t; }" : "=r"(a) : "l"(p));
    return a;
}

#define CP_ASYNC16(dst, src) \
    asm volatile("cp.async.cg.shared.global [%0], [%1], 16;" :: "r"(dst), "l"(src) : "memory")
#define CP_COMMIT() asm volatile("cp.async.commit_group;" ::: "memory")
#define CP_WAIT1()  asm volatile("cp.async.wait_group 1;" ::: "memory")

#define LDSM4(r, addr) \
    asm volatile("ldmatrix.sync.aligned.m8n8.x4.shared.b16 {%0,%1,%2,%3}, [%4];" \
        : "=r"((r)[0]), "=r"((r)[1]), "=r"((r)[2]), "=r"((r)[3]) : "r"(addr))

#define MMA_F16(c, a, b0v, b1v) \
    asm volatile("mma.sync.aligned.m16n8k16.row.col.f32.f16.f16.f32 " \
        "{%0,%1,%2,%3}, {%4,%5,%6,%7}, {%8,%9}, {%0,%1,%2,%3};" \
        : "+f"((c)[0]), "+f"((c)[1]), "+f"((c)[2]), "+f"((c)[3]) \
        : "r"((a)[0]), "r"((a)[1]), "r"((a)[2]), "r"((a)[3]), "r"(b0v), "r"(b1v))

__device__ __forceinline__ float fast_tanh(float x) {
    float r;
    asm("tanh.approx.f32 %0, %1;" : "=f"(r) : "f"(x));
    return r;
}

// ===== prep: f32->f16 (enc + Wh) AND dec_feat in one launch ==============
#define ENC_N4   ((M_ / 4) * D_)
#define ENC_BLKS 4096
#define WH_BLKS  256
#define DF_BLKS  1024
__global__ __launch_bounds__(256)
void prep_kernel(const float* __restrict__ enc, const float* __restrict__ wh,
                 const float* __restrict__ dec, const float* __restrict__ Ws,
                 const float* __restrict__ bs) {
    if (blockIdx.x < ENC_BLKS) {
        __half* dst = g_enc_h;
        const int stride = ENC_BLKS * 256;
        for (int i = blockIdx.x * 256 + threadIdx.x; i < ENC_N4; i += stride) {
            const float4 v = ((const float4*)enc)[i];
            __half2* d = (__half2*)dst + (size_t)i * 2;
            d[0] = __floats2half2_rn(v.x, v.y);
            d[1] = __floats2half2_rn(v.z, v.w);
        }
    } else if (blockIdx.x < ENC_BLKS + WH_BLKS) {
        __half* dst = g_wh_h;
        const int n4 = (D_ / 4) * D_;
        const int stride = WH_BLKS * 256;
        for (int i = (blockIdx.x - ENC_BLKS) * 256 + threadIdx.x; i < n4; i += stride) {
            const float4 v = ((const float4*)wh)[i];
            __half2* d = (__half2*)dst + (size_t)i * 2;
            d[0] = __floats2half2_rn(v.x, v.y);
            d[1] = __floats2half2_rn(v.z, v.w);
        }
    } else {
        // dec_feat: one block per e (256 threads)
        const int e = blockIdx.x - ENC_BLKS - WH_BLKS;
        const int tid = threadIdx.x;
        const float* wrow = Ws + (size_t)e * D_;
        float w4[4];
        #pragma unroll
        for (int j = 0; j < 4; j++) w4[j] = wrow[j * 256 + tid];

        __shared__ float sred[8];
        const int lane = tid & 31, w = tid >> 5;
        const float be = bs[e];

        for (int b = 0; b < B_; b++) {
            const float* drow = dec + (size_t)b * D_;
            float a = 0.f;
            #pragma unroll
            for (int j = 0; j < 4; j++) a = fmaf(w4[j], drow[j * 256 + tid], a);
            #pragma unroll
            for (int off = 16; off > 0; off >>= 1)
                a += __shfl_down_sync(0xffffffffu, a, off);
            if (lane == 0) sred[w] = a;
            __syncthreads();
            if (tid == 0) {
                float t = 0.f;
                #pragma unroll
                for (int k = 0; k < 8; k++) t += sred[k];
                g_dec_feat[b * D_ + e] = t + be;
            }
            __syncthreads();
        }
    }
}

// ================= score GEMM (128x128, 3 stages, 2 CTA/SM) =================
#define BM   128
#define BN   128
#define BK   64
#define STG  3
#define NKT  (D_ / BK)
#define SA_OFF(s) ((s) * 16384)
#define SB_OFF(s) (49152 + (s) * 16384)
#define OFF_DF  98304
#define OFF_WC  (OFF_DF + 512)
#define OFF_V   (OFF_WC + 512)
#define OFF_CV  (OFF_V + 512)
#define OFF_SBF (OFF_CV + 512)
#define SMEM_DYN (OFF_SBF + 2048)

__global__ __launch_bounds__(256, 2)
void score_gemm_kernel(const float* __restrict__ coverage,
                       const float* __restrict__ w_c,
                       const float* __restrict__ v) {
    extern __shared__ __align__(128) char smem[];
    const uint32_t sb = smem_u32(smem);
    const int tid = threadIdx.x, lane = tid & 31, wid = tid >> 5;
    const int wm = wid >> 2, wn = wid & 3;
    const int n0 = blockIdx.x * BN;
    const int m0 = blockIdx.y * BM;

    const __half* A  = g_enc_h;
    const __half* Bw = g_wh_h;

    if (tid < 128) {
        const int e = n0 + tid;
        ((float*)(smem + OFF_DF))[tid] = g_dec_feat[(m0 >> 12) * D_ + e];
        ((float*)(smem + OFF_WC))[tid] = w_c[e];
        ((float*)(smem + OFF_V))[tid]  = v[e];
        ((float*)(smem + OFF_CV))[tid] = coverage[m0 + tid];
    }

    const int a_rowb = wm * 64 + (lane & 15);
    const int a_cofs = lane >> 4;
    const int b_rowb = wn * 32 + ((lane >> 4) << 3) + (lane & 7);
    const int b_cofs = (lane >> 3) & 1;

    float acc[4][4][4];
    #pragma unroll
    for (int i = 0; i < 4; i++)
        #pragma unroll
        for (int j = 0; j < 4; j++)
            #pragma unroll
            for (int k = 0; k < 4; k++) acc[i][j][k] = 0.f;

    auto load_stage = [&](int st, int kt) {
        #pragma unroll
        for (int it = 0; it < 4; it++) {
            const int idx = tid + it * 256;
            const int row = idx >> 3, cb = idx & 7;
            const __half* srcA = A + (size_t)(m0 + row) * D_ + kt * BK + cb * 8;
            const uint32_t dstA = sb + SA_OFF(st) + row * 128 + ((cb ^ (row & 7)) << 4);
            CP_ASYNC16(dstA, srcA);
        }
        #pragma unroll
        for (int it = 0; it < 4; it++) {
            const int idx = tid + it * 256;
            const int row = idx >> 3, cb = idx & 7;
            const __half* srcB = Bw + (size_t)(n0 + row) * D_ + kt * BK + cb * 8;
            const uint32_t dstB = sb + SB_OFF(st) + row * 128 + ((cb ^ (row & 7)) << 4);
            CP_ASYNC16(dstB, srcB);
        }
    };

    load_stage(0, 0); CP_COMMIT();
    load_stage(1, 1); CP_COMMIT();

    for (int kt = 0; kt < NKT; kt++) {
        CP_WAIT1();
        __syncthreads();
        if (kt + 2 < NKT) load_stage((kt + 2) % STG, kt + 2);
        CP_COMMIT();

        const int st = kt % STG;
        const uint32_t aB = sb + SA_OFF(st);
        const uint32_t bB = sb + SB_OFF(st);

        #pragma unroll
        for (int ks = 0; ks < 4; ks++) {
            uint32_t af[4][4], bf[2][4];
            #pragma unroll
            for (int mt = 0; mt < 4; mt++) {
                const int row = a_rowb + mt * 16;
                const int ch  = 2 * ks + a_cofs;
                LDSM4(af[mt], aB + row * 128 + ((ch ^ (row & 7)) << 4));
            }
            #pragma unroll
            for (int p = 0; p < 2; p++) {
                const int row = b_rowb + p * 16;
                const int ch  = 2 * ks + b_cofs;
                LDSM4(bf[p], bB + row * 128 + ((ch ^ (row & 7)) << 4));
            }
            #pragma unroll
            for (int mt = 0; mt < 4; mt++)
                #pragma unroll
                for (int nt = 0; nt < 4; nt++)
                    MMA_F16(acc[mt][nt], af[mt],
                            bf[nt >> 1][(nt & 1) * 2], bf[nt >> 1][(nt & 1) * 2 + 1]);
        }
    }
    __syncthreads();

    const float* sdf  = (const float*)(smem + OFF_DF);
    const float* swc  = (const float*)(smem + OFF_WC);
    const float* sv   = (const float*)(smem + OFF_V);
    const float* scov = (const float*)(smem + OFF_CV);
    float* sbuf = (float*)(smem + OFF_SBF);

    const int g = lane >> 2, tig = lane & 3;
    #pragma unroll
    for (int mt = 0; mt < 4; mt++) {
        #pragma unroll
        for (int h = 0; h < 2; h++) {
            const int rl = wm * 64 + mt * 16 + h * 8 + g;
            const float cov = scov[rl];
            float part = 0.f;
            #pragma unroll
            for (int nt = 0; nt < 4; nt++) {
                #pragma unroll
                for (int q = 0; q < 2; q++) {
                    const int cl = wn * 32 + nt * 8 + tig * 2 + q;
                    const float x = acc[mt][nt][h * 2 + q] + sdf[cl] + cov * swc[cl];
                    part = fmaf(sv[cl], fast_tanh(x), part);
                }
            }
            part += __shfl_down_sync(0xffffffffu, part, 1, 4);
            part += __shfl_down_sync(0xffffffffu, part, 2, 4);
            if (tig == 0) sbuf[rl * 4 + wn] = part;
        }
    }
    __syncthreads();
    if (tid < 128) {
        const float s = sbuf[tid * 4] + sbuf[tid * 4 + 1]
                      + sbuf[tid * 4 + 2] + sbuf[tid * 4 + 3];
        g_score_part[(size_t)blockIdx.x * M_ + m0 + tid] = s;
    }
}

// ===== stats1: sum partials; store masked exp; per-512-chunk (max, sum) =====
__global__ __launch_bounds__(512)
void stats1_kernel(const float* __restrict__ mask) {
    const int b = blockIdx.x, c = blockIdx.y;
    const int tid = threadIdx.x;
    const int idx = b * S_ + c * 512 + tid;

    float sc = 0.f;
    #pragma unroll
    for (int p = 0; p < NBC_; p++) sc += g_score_part[(size_t)p * M_ + idx];

    __shared__ float sh[16];
    const int lane = tid & 31, w = tid >> 5;
    float mx = sc;
    #pragma unroll
    for (int off = 16; off > 0; off >>= 1)
        mx = fmaxf(mx, __shfl_down_sync(0xffffffffu, mx, off));
    if (lane == 0) sh[w] = mx;
    __syncthreads();
    if (tid < 16) {
        float t = sh[tid];
        #pragma unroll
        for (int off = 8; off > 0; off >>= 1)
            t = fmaxf(t, __shfl_down_sync(0xffffu, t, off, 16));
        if (tid == 0) sh[0] = t;
    }
    __syncthreads();
    mx = sh[0];
    __syncthreads();

    float e = expf(sc - mx) * mask[idx];
    g_escore[idx] = e;

    #pragma unroll
    for (int off = 16; off > 0; off >>= 1)
        e += __shfl_down_sync(0xffffffffu, e, off);
    if (lane == 0) sh[w] = e;
    __syncthreads();
    if (tid < 16) {
        float t = sh[tid];
        #pragma unroll
        for (int off = 8; off > 0; off >>= 1)
            t += __shfl_down_sync(0xffffu, t, off, 16);
        if (tid == 0) {
            g_cstat[(b * 8 + c) * 2]     = mx;
            g_cstat[(b * 8 + c) * 2 + 1] = t;
        }
    }
}

// ===== fused batch-stat merge + attn + coverage + context partials =====
// grid (B, 64): 64-s chunks; block 128: tid spans D via uint4 (8 fp16)
__global__ __launch_bounds__(128)
void ctx_part_kernel(const float* __restrict__ coverage,
                     float* __restrict__ attn_out,
                     float* __restrict__ cov_out) {
    const int b  = blockIdx.x;
    const int sc = blockIdx.y;            // 0..63 (64-s chunks)
    const int s0 = sc * 64;
    const int tid = threadIdx.x;

    __shared__ float attn_sm[64];
    __shared__ float s_scale;

    if (tid == 0) {
        float Mx = -1e30f;
        #pragma unroll
        for (int c = 0; c < 8; c++) Mx = fmaxf(Mx, g_cstat[(b * 8 + c) * 2]);
        float T = 0.f;
        #pragma unroll
        for (int c = 0; c < 8; c++)
            T += g_cstat[(b * 8 + c) * 2 + 1] * expf(g_cstat[(b * 8 + c) * 2] - Mx);
        const int myc = sc >> 3;          // 512-chunk containing this 64-chunk
        s_scale = expf(g_cstat[(b * 8 + myc) * 2] - Mx) / T;
    }
    __syncthreads();

    const float scale = s_scale;
    if (tid < 64) {
        const int si = b * S_ + s0 + tid;
        const float a = g_escore[si] * scale;
        attn_sm[tid] = a;
        attn_out[si] = a;
        cov_out[si]  = coverage[si] + a;
    }
    __syncthreads();

    // each thread: 8 consecutive d via uint4, 64 s iterations
    const uint4* ep = (const uint4*)(g_enc_h + ((size_t)b * S_ + s0) * D_) + tid;
    float acc[8];
    #pragma unroll
    for (int i = 0; i < 8; i++) acc[i] = 0.f;

    #pragma unroll 8
    for (int s = 0; s < 64; s++) {
        const float a = attn_sm[s];
        const uint4 e16 = ep[(size_t)s * 128];    // row stride = 1024 fp16 = 128 uint4
        const float2 p0 = __half22float2(*(const __half2*)&e16.x);
        const float2 p1 = __half22float2(*(const __half2*)&e16.y);
        const float2 p2 = __half22float2(*(const __half2*)&e16.z);
        const float2 p3 = __half22float2(*(const __half2*)&e16.w);
        acc[0] = fmaf(a, p0.x, acc[0]);
        acc[1] = fmaf(a, p0.y, acc[1]);
        acc[2] = fmaf(a, p1.x, acc[2]);
        acc[3] = fmaf(a, p1.y, acc[3]);
        acc[4] = fmaf(a, p2.x, acc[4]);
        acc[5] = fmaf(a, p2.y, acc[5]);
        acc[6] = fmaf(a, p3.x, acc[6]);
        acc[7] = fmaf(a, p3.y, acc[7]);
    }

    float4* dst = (float4*)(g_ctx_part + ((size_t)sc * B_ + b) * D_ + tid * 8);
    dst[0] = make_float4(acc[0], acc[1], acc[2], acc[3]);
    dst[1] = make_float4(acc[4], acc[5], acc[6], acc[7]);
}

__global__ void ctx_reduce_kernel(float* __restrict__ ctx_out) {
    const int idx = blockIdx.x * 256 + threadIdx.x;   // < 16384
    float a = 0.f;
    #pragma unroll
    for (int p = 0; p < 64; p++) a += g_ctx_part[(size_t)p * (B_ * D_) + idx];
    ctx_out[idx] = a;
}

// ================= launcher =================
extern "C" void kernel_launch(void* const* d_in, const int* in_sizes, int n_in,
                              void* d_out, int out_size) {
    const float* enc  = (const float*)d_in[0];
    const float* dec  = (const float*)d_in[1];
    const float* mask = (const float*)d_in[2];
    const float* cov  = (const float*)d_in[3];
    const float* Wh   = (const float*)d_in[4];
    const float* Ws   = (const float*)d_in[5];
    const float* bs   = (const float*)d_in[6];
    const float* wc   = (const float*)d_in[7];
    const float* v    = (const float*)d_in[8];

    float* out  = (float*)d_out;
    float* ctx  = out;
    float* attn = out + B_ * D_;
    float* covn = attn + B_ * S_;

    static bool attr_set = false;
    if (!attr_set) {
        cudaFuncSetAttribute(score_gemm_kernel,
                             cudaFuncAttributeMaxDynamicSharedMemorySize, SMEM_DYN);
        attr_set = true;
    }

    prep_kernel<<<ENC_BLKS + WH_BLKS + DF_BLKS, 256>>>(enc, Wh, dec, Ws, bs);
    score_gemm_kernel<<<dim3(D_ / BN, M_ / BM), 256, SMEM_DYN>>>(cov, wc, v);
    stats1_kernel<<<dim3(B_, 8), 512>>>(mask);
    ctx_part_kernel<<<dim3(B_, 64), 128>>>(cov, attn, covn);
    ctx_reduce_kernel<<<64, 256>>>(ctx);
}

// round 15
// speedup vs baseline: 1.1159x; 1.0483x over previous
#include <cuda_runtime.h>
#include <cuda.h>
#include <cuda_fp16.h>
#include <math.h>
#include <stdint.h>

// Problem constants
#define B_   16
#define S_   4096
#define D_   1024
#define M_   (B_ * S_)
#define NBC_ 8               // n partial blocks (1024 / 128)

// ---------------- device scratch ----------------
__device__ float g_dec_feat[B_ * D_];
__device__ float g_score_part[NBC_ * M_];
__device__ float g_escore[M_];            // exp(s - M_chunk) * mask
__device__ float g_cstat[B_ * 8 * 2];     // per-chunk (max, masked exp-sum)
__device__ float g_ctx_part[64 * B_ * D_];
__device__ __align__(16) __half g_enc_h[(size_t)M_ * D_];
__device__ __align__(16) __half g_wh_h[(size_t)D_ * D_];

// ================= PTX helpers (plain sm_100-safe, sm_90-era PTX) =========
__device__ __forceinline__ uint32_t smem_u32(const void* p) {
    uint32_t a;
    asm("{ .reg .u64 t; cvta.to.shared.u64 t, %1; cvt.u32.u64 %0, t; }" : "=r"(a) : "l"(p));
    return a;
}

#define MBAR_INIT(addr, cnt) \
    asm volatile("mbarrier.init.shared.b64 [%0], %1;" :: "r"(addr), "r"(cnt) : "memory")

#define MBAR_EXPECT(addr, tx) \
    asm volatile("mbarrier.arrive.expect_tx.shared.b64 _, [%0], %1;" :: "r"(addr), "r"(tx) : "memory")

#define MBAR_WAITP(addr, ph) do { \
    uint32_t _m = (addr), _p = (ph), _d; \
    asm volatile("{\n\t.reg .pred p;\n\t" \
        "mbarrier.try_wait.parity.acquire.cta.shared::cta.b64 p, [%1], %2;\n\t" \
        "selp.b32 %0, 1, 0, p;\n\t}" : "=r"(_d) : "r"(_m), "r"(_p) : "memory"); \
    if (!_d) { \
        asm volatile("{\n\t.reg .pred P1;\n\t" \
            "WL_%=:\n\t" \
            "mbarrier.try_wait.parity.acquire.cta.shared::cta.b64 P1, [%0], %1, 0x989680;\n\t" \
            "@P1 bra.uni WD_%=;\n\t" \
            "bra.uni WL_%=;\n\t" \
            "WD_%=:\n\t}" :: "r"(_m), "r"(_p) : "memory"); \
    } \
} while (0)

#define TMA_LOAD_2D(smem_addr, map_ptr, cx, cy, mbar) \
    asm volatile("cp.async.bulk.tensor.2d.shared::cta.global.tile.mbarrier::complete_tx::bytes " \
        "[%0], [%1, {%2, %3}], [%4];" \
        :: "r"(smem_addr), "l"((unsigned long long)(map_ptr)), "r"(cx), "r"(cy), "r"(mbar) : "memory")

#define LDSM4(r, addr) \
    asm volatile("ldmatrix.sync.aligned.m8n8.x4.shared.b16 {%0,%1,%2,%3}, [%4];" \
        : "=r"((r)[0]), "=r"((r)[1]), "=r"((r)[2]), "=r"((r)[3]) : "r"(addr))

#define MMA_F16(c, a, b0v, b1v) \
    asm volatile("mma.sync.aligned.m16n8k16.row.col.f32.f16.f16.f32 " \
        "{%0,%1,%2,%3}, {%4,%5,%6,%7}, {%8,%9}, {%0,%1,%2,%3};" \
        : "+f"((c)[0]), "+f"((c)[1]), "+f"((c)[2]), "+f"((c)[3]) \
        : "r"((a)[0]), "r"((a)[1]), "r"((a)[2]), "r"((a)[3]), "r"(b0v), "r"(b1v))

__device__ __forceinline__ float fast_tanh(float x) {
    float r;
    asm("tanh.approx.f32 %0, %1;" : "=f"(r) : "f"(x));
    return r;
}

// ===== prep: f32->f16 (enc + Wh) AND dec_feat in one launch ==============
#define ENC_N4   ((M_ / 4) * D_)
#define ENC_BLKS 4096
#define WH_BLKS  256
#define DF_BLKS  1024
__global__ __launch_bounds__(256)
void prep_kernel(const float* __restrict__ enc, const float* __restrict__ wh,
                 const float* __restrict__ dec, const float* __restrict__ Ws,
                 const float* __restrict__ bs) {
    if (blockIdx.x < ENC_BLKS) {
        __half* dst = g_enc_h;
        const int stride = ENC_BLKS * 256;
        for (int i = blockIdx.x * 256 + threadIdx.x; i < ENC_N4; i += stride) {
            const float4 v = ((const float4*)enc)[i];
            __half2* d = (__half2*)dst + (size_t)i * 2;
            d[0] = __floats2half2_rn(v.x, v.y);
            d[1] = __floats2half2_rn(v.z, v.w);
        }
    } else if (blockIdx.x < ENC_BLKS + WH_BLKS) {
        __half* dst = g_wh_h;
        const int n4 = (D_ / 4) * D_;
        const int stride = WH_BLKS * 256;
        for (int i = (blockIdx.x - ENC_BLKS) * 256 + threadIdx.x; i < n4; i += stride) {
            const float4 v = ((const float4*)wh)[i];
            __half2* d = (__half2*)dst + (size_t)i * 2;
            d[0] = __floats2half2_rn(v.x, v.y);
            d[1] = __floats2half2_rn(v.z, v.w);
        }
    } else {
        const int e = blockIdx.x - ENC_BLKS - WH_BLKS;
        const int tid = threadIdx.x;
        const float* wrow = Ws + (size_t)e * D_;
        float w4[4];
        #pragma unroll
        for (int j = 0; j < 4; j++) w4[j] = wrow[j * 256 + tid];

        __shared__ float sred[8];
        const int lane = tid & 31, w = tid >> 5;
        const float be = bs[e];

        for (int b = 0; b < B_; b++) {
            const float* drow = dec + (size_t)b * D_;
            float a = 0.f;
            #pragma unroll
            for (int j = 0; j < 4; j++) a = fmaf(w4[j], drow[j * 256 + tid], a);
            #pragma unroll
            for (int off = 16; off > 0; off >>= 1)
                a += __shfl_down_sync(0xffffffffu, a, off);
            if (lane == 0) sred[w] = a;
            __syncthreads();
            if (tid == 0) {
                float t = 0.f;
                #pragma unroll
                for (int k = 0; k < 8; k++) t += sred[k];
                g_dec_feat[b * D_ + e] = t + be;
            }
            __syncthreads();
        }
    }
}

// ============ score GEMM: TMA stage fills + mma.sync consumption ============
#define BM   128
#define BN   128
#define BK   64
#define STG  3
#define NKT  (D_ / BK)               // 16
#define TILE_B 16384                 // 128 rows x 128 bytes
#define SA_OFF(s) ((s) * TILE_B)
#define SB_OFF(s) (3 * TILE_B + (s) * TILE_B)
#define OFF_DF  (6 * TILE_B)         // 98304
#define OFF_WC  (OFF_DF + 512)
#define OFF_V   (OFF_WC + 512)
#define OFF_CV  (OFF_V + 512)
#define OFF_SBF (OFF_CV + 512)
#define OFF_MB  (OFF_SBF + 2048)     // 3 mbarriers (8B each)
#define SMEM_DYN (OFF_MB + 64 + 1024)   // +1024 alignment slack

__global__ __launch_bounds__(256, 2)
void score_gemm_kernel(const __grid_constant__ CUtensorMap a_map,
                       const __grid_constant__ CUtensorMap b_map,
                       const float* __restrict__ coverage,
                       const float* __restrict__ w_c,
                       const float* __restrict__ v) {
    extern __shared__ char smem_raw[];
    const uint32_t sb0 = smem_u32(smem_raw);
    const uint32_t sb = (sb0 + 1023u) & ~1023u;    // SW128 atom alignment
    char* smem = smem_raw + (sb - sb0);

    const int tid = threadIdx.x, lane = tid & 31, wid = tid >> 5;
    const int wm = wid >> 2, wn = wid & 3;
    const int n0 = blockIdx.x * BN;
    const int m0 = blockIdx.y * BM;

    if (tid == 0) {
        #pragma unroll
        for (int s = 0; s < STG; s++) MBAR_INIT(sb + OFF_MB + s * 8, 1);
    }
    if (tid < 128) {
        const int e = n0 + tid;
        ((float*)(smem + OFF_DF))[tid] = g_dec_feat[(m0 >> 12) * D_ + e];
        ((float*)(smem + OFF_WC))[tid] = w_c[e];
        ((float*)(smem + OFF_V))[tid]  = v[e];
        ((float*)(smem + OFF_CV))[tid] = coverage[m0 + tid];
    }
    __syncthreads();

    if (tid == 0) {
        MBAR_EXPECT(sb + OFF_MB + 0, 2 * TILE_B);
        TMA_LOAD_2D(sb + SA_OFF(0), &a_map, 0, m0, sb + OFF_MB + 0);
        TMA_LOAD_2D(sb + SB_OFF(0), &b_map, 0, n0, sb + OFF_MB + 0);
        MBAR_EXPECT(sb + OFF_MB + 8, 2 * TILE_B);
        TMA_LOAD_2D(sb + SA_OFF(1), &a_map, BK, m0, sb + OFF_MB + 8);
        TMA_LOAD_2D(sb + SB_OFF(1), &b_map, BK, n0, sb + OFF_MB + 8);
    }

    const int a_rowb = wm * 64 + (lane & 15);
    const int a_cofs = lane >> 4;
    const int b_rowb = wn * 32 + ((lane >> 4) << 3) + (lane & 7);
    const int b_cofs = (lane >> 3) & 1;

    float acc[4][4][4];
    #pragma unroll
    for (int i = 0; i < 4; i++)
        #pragma unroll
        for (int j = 0; j < 4; j++)
            #pragma unroll
            for (int k = 0; k < 4; k++) acc[i][j][k] = 0.f;

    for (int kt = 0; kt < NKT; kt++) {
        const int st = kt % STG;
        // stage st's n-th reuse parity = (kt/3)&1 — stateless
        MBAR_WAITP(sb + OFF_MB + st * 8, (kt / STG) & 1);
        __syncthreads();   // all threads finished consuming stage (kt+2)%3 during kt-1
        if (tid == 0 && kt + 2 < NKT) {
            const int ns = (kt + 2) % STG;
            MBAR_EXPECT(sb + OFF_MB + ns * 8, 2 * TILE_B);
            TMA_LOAD_2D(sb + SA_OFF(ns), &a_map, (kt + 2) * BK, m0, sb + OFF_MB + ns * 8);
            TMA_LOAD_2D(sb + SB_OFF(ns), &b_map, (kt + 2) * BK, n0, sb + OFF_MB + ns * 8);
        }

        const uint32_t aB = sb + SA_OFF(st);
        const uint32_t bB = sb + SB_OFF(st);

        #pragma unroll
        for (int ks = 0; ks < 4; ks++) {
            uint32_t af[4][4], bf[2][4];
            #pragma unroll
            for (int mt = 0; mt < 4; mt++) {
                const int row = a_rowb + mt * 16;
                const int ch  = 2 * ks + a_cofs;
                LDSM4(af[mt], aB + row * 128 + ((ch ^ (row & 7)) << 4));
            }
            #pragma unroll
            for (int p = 0; p < 2; p++) {
                const int row = b_rowb + p * 16;
                const int ch  = 2 * ks + b_cofs;
                LDSM4(bf[p], bB + row * 128 + ((ch ^ (row & 7)) << 4));
            }
            #pragma unroll
            for (int mt = 0; mt < 4; mt++)
                #pragma unroll
                for (int nt = 0; nt < 4; nt++)
                    MMA_F16(acc[mt][nt], af[mt],
                            bf[nt >> 1][(nt & 1) * 2], bf[nt >> 1][(nt & 1) * 2 + 1]);
        }
    }
    __syncthreads();

    // -------- fused epilogue: tanh.approx + v-dot -> per-row partial --------
    const float* sdf  = (const float*)(smem + OFF_DF);
    const float* swc  = (const float*)(smem + OFF_WC);
    const float* sv   = (const float*)(smem + OFF_V);
    const float* scov = (const float*)(smem + OFF_CV);
    float* sbuf = (float*)(smem + OFF_SBF);

    const int g = lane >> 2, tig = lane & 3;
    #pragma unroll
    for (int mt = 0; mt < 4; mt++) {
        #pragma unroll
        for (int h = 0; h < 2; h++) {
            const int rl = wm * 64 + mt * 16 + h * 8 + g;
            const float cov = scov[rl];
            float part = 0.f;
            #pragma unroll
            for (int nt = 0; nt < 4; nt++) {
                #pragma unroll
                for (int q = 0; q < 2; q++) {
                    const int cl = wn * 32 + nt * 8 + tig * 2 + q;
                    const float x = acc[mt][nt][h * 2 + q] + sdf[cl] + cov * swc[cl];
                    part = fmaf(sv[cl], fast_tanh(x), part);
                }
            }
            part += __shfl_down_sync(0xffffffffu, part, 1, 4);
            part += __shfl_down_sync(0xffffffffu, part, 2, 4);
            if (tig == 0) sbuf[rl * 4 + wn] = part;
        }
    }
    __syncthreads();
    if (tid < 128) {
        const float s = sbuf[tid * 4] + sbuf[tid * 4 + 1]
                      + sbuf[tid * 4 + 2] + sbuf[tid * 4 + 3];
        g_score_part[(size_t)blockIdx.x * M_ + m0 + tid] = s;
    }
}

// ===== stats1: sum partials; store masked exp; per-512-chunk (max, sum) =====
__global__ __launch_bounds__(512)
void stats1_kernel(const float* __restrict__ mask) {
    const int b = blockIdx.x, c = blockIdx.y;
    const int tid = threadIdx.x;
    const int idx = b * S_ + c * 512 + tid;

    float sc = 0.f;
    #pragma unroll
    for (int p = 0; p < NBC_; p++) sc += g_score_part[(size_t)p * M_ + idx];

    __shared__ float sh[16];
    const int lane = tid & 31, w = tid >> 5;
    float mx = sc;
    #pragma unroll
    for (int off = 16; off > 0; off >>= 1)
        mx = fmaxf(mx, __shfl_down_sync(0xffffffffu, mx, off));
    if (lane == 0) sh[w] = mx;
    __syncthreads();
    if (tid < 16) {
        float t = sh[tid];
        #pragma unroll
        for (int off = 8; off > 0; off >>= 1)
            t = fmaxf(t, __shfl_down_sync(0xffffu, t, off, 16));
        if (tid == 0) sh[0] = t;
    }
    __syncthreads();
    mx = sh[0];
    __syncthreads();

    float e = expf(sc - mx) * mask[idx];
    g_escore[idx] = e;

    #pragma unroll
    for (int off = 16; off > 0; off >>= 1)
        e += __shfl_down_sync(0xffffffffu, e, off);
    if (lane == 0) sh[w] = e;
    __syncthreads();
    if (tid < 16) {
        float t = sh[tid];
        #pragma unroll
        for (int off = 8; off > 0; off >>= 1)
            t += __shfl_down_sync(0xffffu, t, off, 16);
        if (tid == 0) {
            g_cstat[(b * 8 + c) * 2]     = mx;
            g_cstat[(b * 8 + c) * 2 + 1] = t;
        }
    }
}

// ===== fused batch-stat merge + attn + coverage + context partials =====
__global__ __launch_bounds__(128)
void ctx_part_kernel(const float* __restrict__ coverage,
                     float* __restrict__ attn_out,
                     float* __restrict__ cov_out) {
    const int b  = blockIdx.x;
    const int sc = blockIdx.y;            // 0..63 (64-s chunks)
    const int s0 = sc * 64;
    const int tid = threadIdx.x;

    __shared__ float attn_sm[64];
    __shared__ float s_scale;

    if (tid == 0) {
        float Mx = -1e30f;
        #pragma unroll
        for (int c = 0; c < 8; c++) Mx = fmaxf(Mx, g_cstat[(b * 8 + c) * 2]);
        float T = 0.f;
        #pragma unroll
        for (int c = 0; c < 8; c++)
            T += g_cstat[(b * 8 + c) * 2 + 1] * expf(g_cstat[(b * 8 + c) * 2] - Mx);
        const int myc = sc >> 3;
        s_scale = expf(g_cstat[(b * 8 + myc) * 2] - Mx) / T;
    }
    __syncthreads();

    const float scale = s_scale;
    if (tid < 64) {
        const int si = b * S_ + s0 + tid;
        const float a = g_escore[si] * scale;
        attn_sm[tid] = a;
        attn_out[si] = a;
        cov_out[si]  = coverage[si] + a;
    }
    __syncthreads();

    const uint4* ep = (const uint4*)(g_enc_h + ((size_t)b * S_ + s0) * D_) + tid;
    float acc[8];
    #pragma unroll
    for (int i = 0; i < 8; i++) acc[i] = 0.f;

    #pragma unroll 8
    for (int s = 0; s < 64; s++) {
        const float a = attn_sm[s];
        const uint4 e16 = ep[(size_t)s * 128];
        const float2 p0 = __half22float2(*(const __half2*)&e16.x);
        const float2 p1 = __half22float2(*(const __half2*)&e16.y);
        const float2 p2 = __half22float2(*(const __half2*)&e16.z);
        const float2 p3 = __half22float2(*(const __half2*)&e16.w);
        acc[0] = fmaf(a, p0.x, acc[0]);
        acc[1] = fmaf(a, p0.y, acc[1]);
        acc[2] = fmaf(a, p1.x, acc[2]);
        acc[3] = fmaf(a, p1.y, acc[3]);
        acc[4] = fmaf(a, p2.x, acc[4]);
        acc[5] = fmaf(a, p2.y, acc[5]);
        acc[6] = fmaf(a, p3.x, acc[6]);
        acc[7] = fmaf(a, p3.y, acc[7]);
    }

    float4* dst = (float4*)(g_ctx_part + ((size_t)sc * B_ + b) * D_ + tid * 8);
    dst[0] = make_float4(acc[0], acc[1], acc[2], acc[3]);
    dst[1] = make_float4(acc[4], acc[5], acc[6], acc[7]);
}

__global__ void ctx_reduce_kernel(float* __restrict__ ctx_out) {
    const int idx = blockIdx.x * 256 + threadIdx.x;
    float a = 0.f;
    #pragma unroll
    for (int p = 0; p < 64; p++) a += g_ctx_part[(size_t)p * (B_ * D_) + idx];
    ctx_out[idx] = a;
}

// ================= host: tensor maps + launch =================
typedef CUresult (*PFN_encodeTiled)(
    CUtensorMap*, CUtensorMapDataType, cuuint32_t, void*,
    const cuuint64_t*, const cuuint64_t*, const cuuint32_t*, const cuuint32_t*,
    CUtensorMapInterleave, CUtensorMapSwizzle, CUtensorMapL2promotion,
    CUtensorMapFloatOOBfill);

static PFN_encodeTiled get_encode_fn() {
    void* p = nullptr;
    cudaDriverEntryPointQueryResult qr;
#if CUDART_VERSION >= 12050
    cudaGetDriverEntryPointByVersion("cuTensorMapEncodeTiled", &p, 12000,
                                     cudaEnableDefault, &qr);
#else
    cudaGetDriverEntryPoint("cuTensorMapEncodeTiled", &p, cudaEnableDefault, &qr);
#endif
    return (PFN_encodeTiled)p;
}

static void make_map_2d(PFN_encodeTiled enc_fn, CUtensorMap* map, void* base,
                        unsigned long long rows) {
    cuuint64_t dims[2]    = {(cuuint64_t)D_, (cuuint64_t)rows};
    cuuint64_t strides[1] = {(cuuint64_t)D_ * sizeof(__half)};
    cuuint32_t box[2]     = {BK, 128};        // 64 fp16 = 128B (SW128 limit)
    cuuint32_t estr[2]    = {1, 1};
    enc_fn(map, CU_TENSOR_MAP_DATA_TYPE_FLOAT16, 2, base,
           dims, strides, box, estr,
           CU_TENSOR_MAP_INTERLEAVE_NONE, CU_TENSOR_MAP_SWIZZLE_128B,
           CU_TENSOR_MAP_L2_PROMOTION_L2_128B, CU_TENSOR_MAP_FLOAT_OOB_FILL_NONE);
}

extern "C" void kernel_launch(void* const* d_in, const int* in_sizes, int n_in,
                              void* d_out, int out_size) {
    const float* enc  = (const float*)d_in[0];
    const float* dec  = (const float*)d_in[1];
    const float* mask = (const float*)d_in[2];
    const float* cov  = (const float*)d_in[3];
    const float* Wh   = (const float*)d_in[4];
    const float* Ws   = (const float*)d_in[5];
    const float* bs   = (const float*)d_in[6];
    const float* wc   = (const float*)d_in[7];
    const float* v    = (const float*)d_in[8];

    float* out  = (float*)d_out;
    float* ctx  = out;
    float* attn = out + B_ * D_;
    float* covn = attn + B_ * S_;

    static bool attr_set = false;
    if (!attr_set) {
        cudaFuncSetAttribute(score_gemm_kernel,
                             cudaFuncAttributeMaxDynamicSharedMemorySize, SMEM_DYN);
        attr_set = true;
    }

    void* enc_h = nullptr; void* wh_h = nullptr;
    cudaGetSymbolAddress(&enc_h, g_enc_h);
    cudaGetSymbolAddress(&wh_h, g_wh_h);

    PFN_encodeTiled enc_fn = get_encode_fn();
    CUtensorMap a_map, b_map;
    make_map_2d(enc_fn, &a_map, enc_h, (unsigned long long)M_);
    make_map_2d(enc_fn, &b_map, wh_h, (unsigned long long)D_);

    prep_kernel<<<ENC_BLKS + WH_BLKS + DF_BLKS, 256>>>(enc, Wh, dec, Ws, bs);
    score_gemm_kernel<<<dim3(D_ / BN, M_ / BM), 256, SMEM_DYN>>>(a_map, b_map, cov, wc, v);
    stats1_kernel<<<dim3(B_, 8), 512>>>(mask);
    ctx_part_kernel<<<dim3(B_, 64), 128>>>(cov, attn, covn);
    ctx_reduce_kernel<<<64, 256>>>(ctx);
}

// round 16
// speedup vs baseline: 1.1214x; 1.0049x over previous
#include <cuda_runtime.h>
#include <cuda.h>
#include <cuda_fp16.h>
#include <math.h>
#include <stdint.h>

// Problem constants
#define B_   16
#define S_   4096
#define D_   1024
#define M_   (B_ * S_)
#define NBC_ 8               // n partial blocks (1024 / 128)

// ---------------- device scratch ----------------
__device__ float g_dec_feat[B_ * D_];
__device__ float g_score_part[NBC_ * M_];
__device__ float g_escore[M_];            // exp(s - M_chunk) * mask
__device__ float g_cstat[B_ * 8 * 2];     // per-chunk (max, masked exp-sum)
__device__ float g_ctx_part[64 * B_ * D_];
__device__ __align__(16) __half g_enc_h[(size_t)M_ * D_];
__device__ __align__(16) __half g_wh_h[(size_t)D_ * D_];

// ================= PTX helpers (plain sm_100-safe, sm_90-era PTX) =========
__device__ __forceinline__ uint32_t smem_u32(const void* p) {
    uint32_t a;
    asm("{ .reg .u64 t; cvta.to.shared.u64 t, %1; cvt.u32.u64 %0, t; }" : "=r"(a) : "l"(p));
    return a;
}

#define MBAR_INIT(addr, cnt) \
    asm volatile("mbarrier.init.shared.b64 [%0], %1;" :: "r"(addr), "r"(cnt) : "memory")

#define MBAR_EXPECT(addr, tx) \
    asm volatile("mbarrier.arrive.expect_tx.shared.b64 _, [%0], %1;" :: "r"(addr), "r"(tx) : "memory")

#define MBAR_WAITP(addr, ph) do { \
    uint32_t _m = (addr), _p = (ph), _d; \
    asm volatile("{\n\t.reg .pred p;\n\t" \
        "mbarrier.try_wait.parity.acquire.cta.shared::cta.b64 p, [%1], %2;\n\t" \
        "selp.b32 %0, 1, 0, p;\n\t}" : "=r"(_d) : "r"(_m), "r"(_p) : "memory"); \
    if (!_d) { \
        asm volatile("{\n\t.reg .pred P1;\n\t" \
            "WL_%=:\n\t" \
            "mbarrier.try_wait.parity.acquire.cta.shared::cta.b64 P1, [%0], %1, 0x989680;\n\t" \
            "@P1 bra.uni WD_%=;\n\t" \
            "bra.uni WL_%=;\n\t" \
            "WD_%=:\n\t}" :: "r"(_m), "r"(_p) : "memory"); \
    } \
} while (0)

#define TMA_LOAD_2D(smem_addr, map_ptr, cx, cy, mbar) \
    asm volatile("cp.async.bulk.tensor.2d.shared::cta.global.tile.mbarrier::complete_tx::bytes " \
        "[%0], [%1, {%2, %3}], [%4];" \
        :: "r"(smem_addr), "l"((unsigned long long)(map_ptr)), "r"(cx), "r"(cy), "r"(mbar) : "memory")

#define LDSM4(r, addr) \
    asm volatile("ldmatrix.sync.aligned.m8n8.x4.shared.b16 {%0,%1,%2,%3}, [%4];" \
        : "=r"((r)[0]), "=r"((r)[1]), "=r"((r)[2]), "=r"((r)[3]) : "r"(addr))

#define MMA_F16(c, a, b0v, b1v) \
    asm volatile("mma.sync.aligned.m16n8k16.row.col.f32.f16.f16.f32 " \
        "{%0,%1,%2,%3}, {%4,%5,%6,%7}, {%8,%9}, {%0,%1,%2,%3};" \
        : "+f"((c)[0]), "+f"((c)[1]), "+f"((c)[2]), "+f"((c)[3]) \
        : "r"((a)[0]), "r"((a)[1]), "r"((a)[2]), "r"((a)[3]), "r"(b0v), "r"(b1v))

__device__ __forceinline__ float fast_tanh(float x) {
    float r;
    asm("tanh.approx.f32 %0, %1;" : "=f"(r) : "f"(x));
    return r;
}

// ===== prep: f32->f16 (enc + Wh) AND dec_feat in one launch ==============
#define ENC_N4   ((M_ / 4) * D_)
#define ENC_BLKS 4096
#define WH_BLKS  256
#define DF_BLKS  1024
__global__ __launch_bounds__(256)
void prep_kernel(const float* __restrict__ enc, const float* __restrict__ wh,
                 const float* __restrict__ dec, const float* __restrict__ Ws,
                 const float* __restrict__ bs) {
    if (blockIdx.x < ENC_BLKS) {
        __half* dst = g_enc_h;
        const int stride = ENC_BLKS * 256;
        for (int i = blockIdx.x * 256 + threadIdx.x; i < ENC_N4; i += stride) {
            const float4 v = ((const float4*)enc)[i];
            __half2* d = (__half2*)dst + (size_t)i * 2;
            d[0] = __floats2half2_rn(v.x, v.y);
            d[1] = __floats2half2_rn(v.z, v.w);
        }
    } else if (blockIdx.x < ENC_BLKS + WH_BLKS) {
        __half* dst = g_wh_h;
        const int n4 = (D_ / 4) * D_;
        const int stride = WH_BLKS * 256;
        for (int i = (blockIdx.x - ENC_BLKS) * 256 + threadIdx.x; i < n4; i += stride) {
            const float4 v = ((const float4*)wh)[i];
            __half2* d = (__half2*)dst + (size_t)i * 2;
            d[0] = __floats2half2_rn(v.x, v.y);
            d[1] = __floats2half2_rn(v.z, v.w);
        }
    } else {
        const int e = blockIdx.x - ENC_BLKS - WH_BLKS;
        const int tid = threadIdx.x;
        const float* wrow = Ws + (size_t)e * D_;
        float w4[4];
        #pragma unroll
        for (int j = 0; j < 4; j++) w4[j] = wrow[j * 256 + tid];

        __shared__ float sred[8];
        const int lane = tid & 31, w = tid >> 5;
        const float be = bs[e];

        for (int b = 0; b < B_; b++) {
            const float* drow = dec + (size_t)b * D_;
            float a = 0.f;
            #pragma unroll
            for (int j = 0; j < 4; j++) a = fmaf(w4[j], drow[j * 256 + tid], a);
            #pragma unroll
            for (int off = 16; off > 0; off >>= 1)
                a += __shfl_down_sync(0xffffffffu, a, off);
            if (lane == 0) sred[w] = a;
            __syncthreads();
            if (tid == 0) {
                float t = 0.f;
                #pragma unroll
                for (int k = 0; k < 8; k++) t += sred[k];
                g_dec_feat[b * D_ + e] = t + be;
            }
            __syncthreads();
        }
    }
}

// ============ score GEMM: TMA stage fills + mma.sync consumption ============
#define BM   128
#define BN   128
#define BK   64
#define STG  3
#define NKT  (D_ / BK)               // 16
#define TILE_B 16384                 // 128 rows x 128 bytes
#define SA_OFF(s) ((s) * TILE_B)
#define SB_OFF(s) (3 * TILE_B + (s) * TILE_B)
#define OFF_DF  (6 * TILE_B)         // 98304
#define OFF_WC  (OFF_DF + 512)
#define OFF_V   (OFF_WC + 512)
#define OFF_CV  (OFF_V + 512)
#define OFF_SBF (OFF_CV + 512)
#define OFF_MB  (OFF_SBF + 2048)     // 3 mbarriers (8B each)
#define SMEM_DYN (OFF_MB + 64 + 1024)   // +1024 alignment slack

__global__ __launch_bounds__(256, 2)
void score_gemm_kernel(const __grid_constant__ CUtensorMap a_map,
                       const __grid_constant__ CUtensorMap b_map,
                       const float* __restrict__ coverage,
                       const float* __restrict__ w_c,
                       const float* __restrict__ v) {
    extern __shared__ char smem_raw[];
    const uint32_t sb0 = smem_u32(smem_raw);
    const uint32_t sb = (sb0 + 1023u) & ~1023u;    // SW128 atom alignment
    char* smem = smem_raw + (sb - sb0);

    const int tid = threadIdx.x, lane = tid & 31, wid = tid >> 5;
    const int wm = wid >> 2, wn = wid & 3;
    const int n0 = blockIdx.x * BN;
    const int m0 = blockIdx.y * BM;

    if (tid == 0) {
        #pragma unroll
        for (int s = 0; s < STG; s++) MBAR_INIT(sb + OFF_MB + s * 8, 1);
    }
    if (tid < 128) {
        const int e = n0 + tid;
        ((float*)(smem + OFF_DF))[tid] = g_dec_feat[(m0 >> 12) * D_ + e];
        ((float*)(smem + OFF_WC))[tid] = w_c[e];
        ((float*)(smem + OFF_V))[tid]  = v[e];
        ((float*)(smem + OFF_CV))[tid] = coverage[m0 + tid];
    }
    __syncthreads();

    if (tid == 0) {
        MBAR_EXPECT(sb + OFF_MB + 0, 2 * TILE_B);
        TMA_LOAD_2D(sb + SA_OFF(0), &a_map, 0, m0, sb + OFF_MB + 0);
        TMA_LOAD_2D(sb + SB_OFF(0), &b_map, 0, n0, sb + OFF_MB + 0);
        MBAR_EXPECT(sb + OFF_MB + 8, 2 * TILE_B);
        TMA_LOAD_2D(sb + SA_OFF(1), &a_map, BK, m0, sb + OFF_MB + 8);
        TMA_LOAD_2D(sb + SB_OFF(1), &b_map, BK, n0, sb + OFF_MB + 8);
    }

    const int a_rowb = wm * 64 + (lane & 15);
    const int a_cofs = lane >> 4;
    const int b_rowb = wn * 32 + ((lane >> 4) << 3) + (lane & 7);
    const int b_cofs = (lane >> 3) & 1;

    float acc[4][4][4];
    #pragma unroll
    for (int i = 0; i < 4; i++)
        #pragma unroll
        for (int j = 0; j < 4; j++)
            #pragma unroll
            for (int k = 0; k < 4; k++) acc[i][j][k] = 0.f;

    for (int kt = 0; kt < NKT; kt++) {
        const int st = kt % STG;
        // stage st's n-th reuse parity = (kt/3)&1 — stateless
        MBAR_WAITP(sb + OFF_MB + st * 8, (kt / STG) & 1);
        __syncthreads();   // all threads finished consuming stage (kt+2)%3 during kt-1
        if (tid == 0 && kt + 2 < NKT) {
            const int ns = (kt + 2) % STG;
            MBAR_EXPECT(sb + OFF_MB + ns * 8, 2 * TILE_B);
            TMA_LOAD_2D(sb + SA_OFF(ns), &a_map, (kt + 2) * BK, m0, sb + OFF_MB + ns * 8);
            TMA_LOAD_2D(sb + SB_OFF(ns), &b_map, (kt + 2) * BK, n0, sb + OFF_MB + ns * 8);
        }

        const uint32_t aB = sb + SA_OFF(st);
        const uint32_t bB = sb + SB_OFF(st);

        #pragma unroll
        for (int ks = 0; ks < 4; ks++) {
            uint32_t af[4][4], bf[2][4];
            #pragma unroll
            for (int mt = 0; mt < 4; mt++) {
                const int row = a_rowb + mt * 16;
                const int ch  = 2 * ks + a_cofs;
                LDSM4(af[mt], aB + row * 128 + ((ch ^ (row & 7)) << 4));
            }
            #pragma unroll
            for (int p = 0; p < 2; p++) {
                const int row = b_rowb + p * 16;
                const int ch  = 2 * ks + b_cofs;
                LDSM4(bf[p], bB + row * 128 + ((ch ^ (row & 7)) << 4));
            }
            #pragma unroll
            for (int mt = 0; mt < 4; mt++)
                #pragma unroll
                for (int nt = 0; nt < 4; nt++)
                    MMA_F16(acc[mt][nt], af[mt],
                            bf[nt >> 1][(nt & 1) * 2], bf[nt >> 1][(nt & 1) * 2 + 1]);
        }
    }
    __syncthreads();

    // -------- fused epilogue: tanh.approx + v-dot -> per-row partial --------
    const float* sdf  = (const float*)(smem + OFF_DF);
    const float* swc  = (const float*)(smem + OFF_WC);
    const float* sv   = (const float*)(smem + OFF_V);
    const float* scov = (const float*)(smem + OFF_CV);
    float* sbuf = (float*)(smem + OFF_SBF);

    const int g = lane >> 2, tig = lane & 3;
    #pragma unroll
    for (int mt = 0; mt < 4; mt++) {
        #pragma unroll
        for (int h = 0; h < 2; h++) {
            const int rl = wm * 64 + mt * 16 + h * 8 + g;
            const float cov = scov[rl];
            float part = 0.f;
            #pragma unroll
            for (int nt = 0; nt < 4; nt++) {
                #pragma unroll
                for (int q = 0; q < 2; q++) {
                    const int cl = wn * 32 + nt * 8 + tig * 2 + q;
                    const float x = acc[mt][nt][h * 2 + q] + sdf[cl] + cov * swc[cl];
                    part = fmaf(sv[cl], fast_tanh(x), part);
                }
            }
            part += __shfl_down_sync(0xffffffffu, part, 1, 4);
            part += __shfl_down_sync(0xffffffffu, part, 2, 4);
            if (tig == 0) sbuf[rl * 4 + wn] = part;
        }
    }
    __syncthreads();
    if (tid < 128) {
        const float s = sbuf[tid * 4] + sbuf[tid * 4 + 1]
                      + sbuf[tid * 4 + 2] + sbuf[tid * 4 + 3];
        g_score_part[(size_t)blockIdx.x * M_ + m0 + tid] = s;
    }
}

// ===== stats1: sum partials; store masked exp; per-512-chunk (max, sum) =====
__global__ __launch_bounds__(512)
void stats1_kernel(const float* __restrict__ mask) {
    const int b = blockIdx.x, c = blockIdx.y;
    const int tid = threadIdx.x;
    const int idx = b * S_ + c * 512 + tid;

    float sc = 0.f;
    #pragma unroll
    for (int p = 0; p < NBC_; p++) sc += g_score_part[(size_t)p * M_ + idx];

    __shared__ float sh[16];
    const int lane = tid & 31, w = tid >> 5;
    float mx = sc;
    #pragma unroll
    for (int off = 16; off > 0; off >>= 1)
        mx = fmaxf(mx, __shfl_down_sync(0xffffffffu, mx, off));
    if (lane == 0) sh[w] = mx;
    __syncthreads();
    if (tid < 16) {
        float t = sh[tid];
        #pragma unroll
        for (int off = 8; off > 0; off >>= 1)
            t = fmaxf(t, __shfl_down_sync(0xffffu, t, off, 16));
        if (tid == 0) sh[0] = t;
    }
    __syncthreads();
    mx = sh[0];
    __syncthreads();

    float e = expf(sc - mx) * mask[idx];
    g_escore[idx] = e;

    #pragma unroll
    for (int off = 16; off > 0; off >>= 1)
        e += __shfl_down_sync(0xffffffffu, e, off);
    if (lane == 0) sh[w] = e;
    __syncthreads();
    if (tid < 16) {
        float t = sh[tid];
        #pragma unroll
        for (int off = 8; off > 0; off >>= 1)
            t += __shfl_down_sync(0xffffu, t, off, 16);
        if (tid == 0) {
            g_cstat[(b * 8 + c) * 2]     = mx;
            g_cstat[(b * 8 + c) * 2 + 1] = t;
        }
    }
}

// ===== fused batch-stat merge + attn + coverage + context partials =====
__global__ __launch_bounds__(128)
void ctx_part_kernel(const float* __restrict__ coverage,
                     float* __restrict__ attn_out,
                     float* __restrict__ cov_out) {
    const int b  = blockIdx.x;
    const int sc = blockIdx.y;            // 0..63 (64-s chunks)
    const int s0 = sc * 64;
    const int tid = threadIdx.x;

    __shared__ float attn_sm[64];
    __shared__ float s_scale;

    if (tid == 0) {
        float Mx = -1e30f;
        #pragma unroll
        for (int c = 0; c < 8; c++) Mx = fmaxf(Mx, g_cstat[(b * 8 + c) * 2]);
        float T = 0.f;
        #pragma unroll
        for (int c = 0; c < 8; c++)
            T += g_cstat[(b * 8 + c) * 2 + 1] * expf(g_cstat[(b * 8 + c) * 2] - Mx);
        const int myc = sc >> 3;
        s_scale = expf(g_cstat[(b * 8 + myc) * 2] - Mx) / T;
    }
    __syncthreads();

    const float scale = s_scale;
    if (tid < 64) {
        const int si = b * S_ + s0 + tid;
        const float a = g_escore[si] * scale;
        attn_sm[tid] = a;
        attn_out[si] = a;
        cov_out[si]  = coverage[si] + a;
    }
    __syncthreads();

    const uint4* ep = (const uint4*)(g_enc_h + ((size_t)b * S_ + s0) * D_) + tid;
    float acc[8];
    #pragma unroll
    for (int i = 0; i < 8; i++) acc[i] = 0.f;

    #pragma unroll 8
    for (int s = 0; s < 64; s++) {
        const float a = attn_sm[s];
        const uint4 e16 = ep[(size_t)s * 128];
        const float2 p0 = __half22float2(*(const __half2*)&e16.x);
        const float2 p1 = __half22float2(*(const __half2*)&e16.y);
        const float2 p2 = __half22float2(*(const __half2*)&e16.z);
        const float2 p3 = __half22float2(*(const __half2*)&e16.w);
        acc[0] = fmaf(a, p0.x, acc[0]);
        acc[1] = fmaf(a, p0.y, acc[1]);
        acc[2] = fmaf(a, p1.x, acc[2]);
        acc[3] = fmaf(a, p1.y, acc[3]);
        acc[4] = fmaf(a, p2.x, acc[4]);
        acc[5] = fmaf(a, p2.y, acc[5]);
        acc[6] = fmaf(a, p3.x, acc[6]);
        acc[7] = fmaf(a, p3.y, acc[7]);
    }

    float4* dst = (float4*)(g_ctx_part + ((size_t)sc * B_ + b) * D_ + tid * 8);
    dst[0] = make_float4(acc[0], acc[1], acc[2], acc[3]);
    dst[1] = make_float4(acc[4], acc[5], acc[6], acc[7]);
}

__global__ void ctx_reduce_kernel(float* __restrict__ ctx_out) {
    const int idx = blockIdx.x * 256 + threadIdx.x;
    float a = 0.f;
    #pragma unroll
    for (int p = 0; p < 64; p++) a += g_ctx_part[(size_t)p * (B_ * D_) + idx];
    ctx_out[idx] = a;
}

// ================= host: tensor maps + launch =================
typedef CUresult (*PFN_encodeTiled)(
    CUtensorMap*, CUtensorMapDataType, cuuint32_t, void*,
    const cuuint64_t*, const cuuint64_t*, const cuuint32_t*, const cuuint32_t*,
    CUtensorMapInterleave, CUtensorMapSwizzle, CUtensorMapL2promotion,
    CUtensorMapFloatOOBfill);

static PFN_encodeTiled get_encode_fn() {
    void* p = nullptr;
    cudaDriverEntryPointQueryResult qr;
#if CUDART_VERSION >= 12050
    cudaGetDriverEntryPointByVersion("cuTensorMapEncodeTiled", &p, 12000,
                                     cudaEnableDefault, &qr);
#else
    cudaGetDriverEntryPoint("cuTensorMapEncodeTiled", &p, cudaEnableDefault, &qr);
#endif
    return (PFN_encodeTiled)p;
}

static void make_map_2d(PFN_encodeTiled enc_fn, CUtensorMap* map, void* base,
                        unsigned long long rows) {
    cuuint64_t dims[2]    = {(cuuint64_t)D_, (cuuint64_t)rows};
    cuuint64_t strides[1] = {(cuuint64_t)D_ * sizeof(__half)};
    cuuint32_t box[2]     = {BK, 128};        // 64 fp16 = 128B (SW128 limit)
    cuuint32_t estr[2]    = {1, 1};
    enc_fn(map, CU_TENSOR_MAP_DATA_TYPE_FLOAT16, 2, base,
           dims, strides, box, estr,
           CU_TENSOR_MAP_INTERLEAVE_NONE, CU_TENSOR_MAP_SWIZZLE_128B,
           CU_TENSOR_MAP_L2_PROMOTION_L2_128B, CU_TENSOR_MAP_FLOAT_OOB_FILL_NONE);
}

extern "C" void kernel_launch(void* const* d_in, const int* in_sizes, int n_in,
                              void* d_out, int out_size) {
    const float* enc  = (const float*)d_in[0];
    const float* dec  = (const float*)d_in[1];
    const float* mask = (const float*)d_in[2];
    const float* cov  = (const float*)d_in[3];
    const float* Wh   = (const float*)d_in[4];
    const float* Ws   = (const float*)d_in[5];
    const float* bs   = (const float*)d_in[6];
    const float* wc   = (const float*)d_in[7];
    const float* v    = (const float*)d_in[8];

    float* out  = (float*)d_out;
    float* ctx  = out;
    float* attn = out + B_ * D_;
    float* covn = attn + B_ * S_;

    static bool attr_set = false;
    if (!attr_set) {
        cudaFuncSetAttribute(score_gemm_kernel,
                             cudaFuncAttributeMaxDynamicSharedMemorySize, SMEM_DYN);
        attr_set = true;
    }

    void* enc_h = nullptr; void* wh_h = nullptr;
    cudaGetSymbolAddress(&enc_h, g_enc_h);
    cudaGetSymbolAddress(&wh_h, g_wh_h);

    PFN_encodeTiled enc_fn = get_encode_fn();
    CUtensorMap a_map, b_map;
    make_map_2d(enc_fn, &a_map, enc_h, (unsigned long long)M_);
    make_map_2d(enc_fn, &b_map, wh_h, (unsigned long long)D_);

    prep_kernel<<<ENC_BLKS + WH_BLKS + DF_BLKS, 256>>>(enc, Wh, dec, Ws, bs);
    score_gemm_kernel<<<dim3(D_ / BN, M_ / BM), 256, SMEM_DYN>>>(a_map, b_map, cov, wc, v);
    stats1_kernel<<<dim3(B_, 8), 512>>>(mask);
    ctx_part_kernel<<<dim3(B_, 64), 128>>>(cov, attn, covn);
    ctx_reduce_kernel<<<64, 256>>>(ctx);
}